// round 5
// baseline (speedup 1.0000x reference)
#include <cuda_runtime.h>
#include <cuda_fp16.h>

#define NPTS 1000000
#define DX 300
#define DY 300
#define DZ 300
#define RNK  48
#define PSTR 64    // padded halves per plane cell (128 B, line-aligned)
#define NC   27

// fp16 planes (cell-major, 64-half padded rows), fp32 vectors (cell-major, 48 floats)
__device__ __align__(16) __half g_xyH[DX * DY * PSTR];
__device__ __align__(16) __half g_xzH[DX * DZ * PSTR];
__device__ __align__(16) __half g_yzH[DY * DZ * PSTR];
__device__ __align__(16) float  g_xvT[DX * RNK];
__device__ __align__(16) float  g_yvT[DY * RNK];
__device__ __align__(16) float  g_zvT[DZ * RNK];

typedef unsigned long long u64;

// ---------- packed f32x2 helpers ----------
__device__ __forceinline__ u64 pk2(float lo, float hi) {
    u64 r;
    asm("mov.b64 %0, {%1, %2};" : "=l"(r) : "f"(lo), "f"(hi));
    return r;
}
__device__ __forceinline__ void upk2(u64 v, float& lo, float& hi) {
    asm("mov.b64 {%0, %1}, %2;" : "=f"(lo), "=f"(hi) : "l"(v));
}
__device__ __forceinline__ u64 f2mul(u64 a, u64 b) {
    u64 d;
    asm("mul.rn.f32x2 %0, %1, %2;" : "=l"(d) : "l"(a), "l"(b));
    return d;
}
__device__ __forceinline__ u64 f2add(u64 a, u64 b) {
    u64 d;
    asm("add.rn.f32x2 %0, %1, %2;" : "=l"(d) : "l"(a), "l"(b));
    return d;
}
__device__ __forceinline__ u64 f2fma(u64 a, u64 b, u64 c) {
    u64 d;
    asm("fma.rn.f32x2 %0, %1, %2, %3;" : "=l"(d) : "l"(a), "l"(b), "l"(c));
    return d;
}
__device__ __forceinline__ u64 h2f2(unsigned int h) {
    float2 f = __half22float2(*(__half2*)&h);
    return pk2(f.x, f.y);
}

// ---------- merged transpose/convert: [RNK][cells] -> fp16 [cells][PSTR] (planes)
//                                                   -> fp32 [cells][RNK]  (vectors)
__global__ void __launch_bounds__(128) transpose_all(
    const float* __restrict__ xy, const float* __restrict__ xz,
    const float* __restrict__ yz, const float* __restrict__ xv,
    const float* __restrict__ yv, const float* __restrict__ zv)
{
    __shared__ float tile[RNK][129];
    int b = blockIdx.x;
    int t = threadIdx.x;

    if (b < 2112) {
        const float* src;
        __half* dst;
        int base;
        const int cells = DX * DY;     // 90000 for every plane
        if (b < 704)       { src = xy; dst = g_xyH; base = b * 128; }
        else if (b < 1408) { src = xz; dst = g_xzH; base = (b - 704) * 128; }
        else               { src = yz; dst = g_yzH; base = (b - 1408) * 128; }

        int nc = cells - base;
        if (nc > 128) nc = 128;

        #pragma unroll
        for (int r = 0; r < RNK; r++) {
            if (t < nc) tile[r][t] = src[r * cells + base + t];
        }
        __syncthreads();
        __half2* dst2 = (__half2*)dst;
        for (int i = t; i < nc * 32; i += 128) {   // 32 half2 per cell
            int cl = i >> 5;
            int p  = i & 31;
            float lo = (2 * p     < RNK) ? tile[2 * p][cl]     : 0.0f;
            float hi = (2 * p + 1 < RNK) ? tile[2 * p + 1][cl] : 0.0f;
            dst2[(u64)(base + cl) * 32 + p] = __floats2half2_rn(lo, hi);
        }
    } else {
        int vb = b - 2112;
        int vi = vb / 3;
        int base = (vb % 3) * 128;
        const int cells = DX;          // 300 for every vector
        const float* src = (vi == 0) ? xv : ((vi == 1) ? yv : zv);
        float* dst = (vi == 0) ? g_xvT : ((vi == 1) ? g_yvT : g_zvT);

        int nc = cells - base;
        if (nc > 128) nc = 128;
        if (nc <= 0) return;

        #pragma unroll
        for (int r = 0; r < RNK; r++) {
            if (t < nc) tile[r][t] = src[r * cells + base + t];
        }
        __syncthreads();
        for (int i = t; i < nc * RNK; i += 128) {
            int cl = i / RNK;
            int r  = i - cl * RNK;
            dst[(base + cl) * RNK + r] = tile[r][cl];
        }
    }
}

__device__ __forceinline__ void prep_coord(float g, int L, int& i0, int& i1, float& f)
{
    float t  = (g + 1.0f) * 0.5f;
    float ih = t * (float)(L - 1);
    int i = (int)floorf(ih);
    i = max(0, min(i, L - 1));
    i0 = i;
    i1 = min(i + 1, L - 1);
    f = ih - (float)i;
}

// one plane-corner gather for lane s: 16B (ranks 8s..8s+7) + 8B (ranks 32+4s..+3)
struct PC { uint4 a; uint2 b; };
__device__ __forceinline__ PC ldpc(const __half* cell, int s)
{
    PC r;
    r.a = *(const uint4*)((const char*)cell + s * 16);
    r.b = *(const uint2*)((const char*)cell + 64 + s * 8);
    return r;
}

// matvec: acc += f * Frow[0..27]
__device__ __forceinline__ void mv(const float* __restrict__ row, float f, u64* acc)
{
    u64 F2 = pk2(f, f);
    const ulonglong2* Fr = (const ulonglong2*)row;
    #pragma unroll
    for (int m = 0; m < 7; m++) {
        ulonglong2 q = Fr[m];
        acc[m * 2 + 0] = f2fma(F2, q.x, acc[m * 2 + 0]);
        acc[m * 2 + 1] = f2fma(F2, q.y, acc[m * 2 + 1]);
    }
}

// one segment: fp16 bilinear corners (already loaded) * fp32 vec lerp -> matvec
__device__ __forceinline__ void do_seg(
    const PC& c00, const PC& c01, const PC& c10, const PC& c11,
    const float* __restrict__ vbase0, const float* __restrict__ vbase1, int s,
    float fh, float fw, float fv,
    const float* __restrict__ sFseg, u64* acc)
{
    float w00 = (1.0f - fh) * (1.0f - fw);
    float w01 = (1.0f - fh) * fw;
    float w10 = fh * (1.0f - fw);
    float w11 = fh * fw;
    u64 W00 = pk2(w00, w00), W01 = pk2(w01, w01);
    u64 W10 = pk2(w10, w10), W11 = pk2(w11, w11);
    u64 FV  = pk2(fv, fv),  GV = pk2(1.0f - fv, 1.0f - fv);

    // vectors: chunkA ranks 8s..8s+7, chunkB ranks 32+4s..+3
    float4 u0 = *(const float4*)(vbase0 + 8 * s);
    float4 u1 = *(const float4*)(vbase0 + 8 * s + 4);
    float4 ub = *(const float4*)(vbase0 + 32 + 4 * s);
    float4 q0 = *(const float4*)(vbase1 + 8 * s);
    float4 q1 = *(const float4*)(vbase1 + 8 * s + 4);
    float4 qb = *(const float4*)(vbase1 + 32 + 4 * s);

    // ---- chunk A: 4 packed pairs (ranks 8s+2k, 8s+2k+1) ----
    const unsigned int* a00 = (const unsigned int*)&c00.a;
    const unsigned int* a01 = (const unsigned int*)&c01.a;
    const unsigned int* a10 = (const unsigned int*)&c10.a;
    const unsigned int* a11 = (const unsigned int*)&c11.a;
    u64 UA[4] = { pk2(u0.x, u0.y), pk2(u0.z, u0.w), pk2(u1.x, u1.y), pk2(u1.z, u1.w) };
    u64 QA[4] = { pk2(q0.x, q0.y), pk2(q0.z, q0.w), pk2(q1.x, q1.y), pk2(q1.z, q1.w) };

    #pragma unroll
    for (int k = 0; k < 4; k++) {
        u64 t = f2mul(W00, h2f2(a00[k]));
        t = f2fma(W01, h2f2(a01[k]), t);
        t = f2fma(W10, h2f2(a10[k]), t);
        t = f2fma(W11, h2f2(a11[k]), t);
        u64 v = f2fma(FV, QA[k], f2mul(GV, UA[k]));
        u64 fe = f2mul(t, v);
        float flo, fhi;
        upk2(fe, flo, fhi);
        // rows: e=2k -> slot 8k+s ; e=2k+1 -> slot 8k+4+s
        mv(sFseg + (8 * k + s) * 28, flo, acc);
        mv(sFseg + (8 * k + 4 + s) * 28, fhi, acc);
    }

    // ---- chunk B: 2 packed pairs (ranks 32+4s+2k, +2k+1) ----
    const unsigned int* b00 = (const unsigned int*)&c00.b;
    const unsigned int* b01 = (const unsigned int*)&c01.b;
    const unsigned int* b10 = (const unsigned int*)&c10.b;
    const unsigned int* b11 = (const unsigned int*)&c11.b;
    u64 UB[2] = { pk2(ub.x, ub.y), pk2(ub.z, ub.w) };
    u64 QB[2] = { pk2(qb.x, qb.y), pk2(qb.z, qb.w) };

    #pragma unroll
    for (int k = 0; k < 2; k++) {
        u64 t = f2mul(W00, h2f2(b00[k]));
        t = f2fma(W01, h2f2(b01[k]), t);
        t = f2fma(W10, h2f2(b10[k]), t);
        t = f2fma(W11, h2f2(b11[k]), t);
        u64 v = f2fma(FV, QB[k], f2mul(GV, UB[k]));
        u64 fe = f2mul(t, v);
        float flo, fhi;
        upk2(fe, flo, fhi);
        // rows: slot 32+8k+s and 36+8k+s
        mv(sFseg + (32 + 8 * k + s) * 28, flo, acc);
        mv(sFseg + (36 + 8 * k + s) * 28, fhi, acc);
    }
}

__global__ void __launch_bounds__(256, 2) sample_kernel(
    const float* __restrict__ xyz, const float* __restrict__ fvec,
    float* __restrict__ out)
{
    // sF: permuted padded F (144 x 28). Reused as output staging after matvec.
    __shared__ __align__(16) float sF[144 * 28];
    __shared__ float sXYZ[64 * 3];

    int tid  = threadIdx.x;
    int lane = tid & 31;
    int warp = tid >> 5;
    int s    = lane & 3;
    int pw   = lane >> 2;
    int pp   = warp * 8 + pw;
    int base = blockIdx.x * 64;

    // Permutation: within each 48-row segment block, rows rr<32 (chunkA, rr=8s+e)
    // go to slot 4e+s; rows rr>=32 (chunkB, rr=32+4s+e) go to slot 32+4e+s.
    for (int i = tid; i < 144 * 28; i += 256) {
        int r = i / 28;
        int c = i - r * 28;
        int seg = r / 48;
        int rr  = r - seg * 48;
        int slot;
        if (rr < 32) slot = seg * 48 + ((rr & 7) << 2) + (rr >> 3);
        else { int tb = rr - 32; slot = seg * 48 + 32 + ((tb & 3) << 2) + (tb >> 2); }
        sF[slot * 28 + c] = (c < NC) ? fvec[r * NC + c] : 0.0f;
    }
    if (tid < 192) sXYZ[tid] = xyz[base * 3 + tid];
    __syncthreads();

    float x = sXYZ[pp * 3 + 0];
    float y = sXYZ[pp * 3 + 1];
    float z = sXYZ[pp * 3 + 2];

    int ix0, ix1, iy0, iy1, iz0, iz1;
    float fx, fy, fz;
    prep_coord(x * 2.0f - 1.0f, DX, ix0, ix1, fx);
    prep_coord(y * 2.0f - 1.0f, DY, iy0, iy1, fy);
    prep_coord(z * 2.0f - 1.0f, DZ, iz0, iz1, fz);

    u64 acc[14];
    #pragma unroll
    for (int c = 0; c < 14; c++) acc[c] = 0ULL;

    // ---- software-pipelined gathers: load seg k+1 before computing seg k ----
    // seg0: xy plane
    PC c00 = ldpc(g_xyH + (u64)(ix0 * DY + iy0) * PSTR, s);
    PC c01 = ldpc(g_xyH + (u64)(ix0 * DY + iy1) * PSTR, s);
    PC c10 = ldpc(g_xyH + (u64)(ix1 * DY + iy0) * PSTR, s);
    PC c11 = ldpc(g_xyH + (u64)(ix1 * DY + iy1) * PSTR, s);

    // prefetch seg1: xz plane
    PC n00 = ldpc(g_xzH + (u64)(ix0 * DZ + iz0) * PSTR, s);
    PC n01 = ldpc(g_xzH + (u64)(ix0 * DZ + iz1) * PSTR, s);
    PC n10 = ldpc(g_xzH + (u64)(ix1 * DZ + iz0) * PSTR, s);
    PC n11 = ldpc(g_xzH + (u64)(ix1 * DZ + iz1) * PSTR, s);

    do_seg(c00, c01, c10, c11, g_zvT + iz0 * RNK, g_zvT + iz1 * RNK, s,
           fx, fy, fz, sF, acc);

    // prefetch seg2: yz plane
    c00 = ldpc(g_yzH + (u64)(iy0 * DZ + iz0) * PSTR, s);
    c01 = ldpc(g_yzH + (u64)(iy0 * DZ + iz1) * PSTR, s);
    c10 = ldpc(g_yzH + (u64)(iy1 * DZ + iz0) * PSTR, s);
    c11 = ldpc(g_yzH + (u64)(iy1 * DZ + iz1) * PSTR, s);

    do_seg(n00, n01, n10, n11, g_yvT + iy0 * RNK, g_yvT + iy1 * RNK, s,
           fx, fz, fy, sF + 48 * 28, acc);

    do_seg(c00, c01, c10, c11, g_xvT + ix0 * RNK, g_xvT + ix1 * RNK, s,
           fy, fz, fx, sF + 96 * 28, acc);

    // reduce across the 4 lanes of each point
    #pragma unroll
    for (int m = 0; m < 14; m++) {
        u64 t = __shfl_xor_sync(0xffffffffu, acc[m], 1);
        acc[m] = f2add(acc[m], t);
        t = __shfl_xor_sync(0xffffffffu, acc[m], 2);
        acc[m] = f2add(acc[m], t);
    }

    __syncthreads();   // all matvec reads of sF done; reuse as staging

    if (s == 0) {
        u64* dst = (u64*)(sF + pp * 28);
        #pragma unroll
        for (int m = 0; m < 14; m++) dst[m] = acc[m];  // slot 27 junk, never read
    }
    __syncthreads();

    #pragma unroll 2
    for (int i = tid; i < 64 * NC; i += 256) {
        int pt = i / NC;
        int c  = i - pt * NC;
        out[base * NC + i] = sF[pt * 28 + c];
    }
}

extern "C" void kernel_launch(void* const* d_in, const int* in_sizes, int n_in,
                              void* d_out, int out_size)
{
    const float* xyz = (const float*)d_in[0];
    const float* xyp = (const float*)d_in[1];
    const float* xzp = (const float*)d_in[2];
    const float* yzp = (const float*)d_in[3];
    const float* xv  = (const float*)d_in[4];
    const float* yv  = (const float*)d_in[5];
    const float* zv  = (const float*)d_in[6];
    const float* fv  = (const float*)d_in[7];
    float* out = (float*)d_out;

    transpose_all<<<2121, 128>>>(xyp, xzp, yzp, xv, yv, zv);
    sample_kernel<<<NPTS / 64, 256>>>(xyz, fv, out);
}

// round 6
// speedup vs baseline: 1.0005x; 1.0005x over previous
#include <cuda_runtime.h>
#include <cuda_fp16.h>

#define NPTS 1000000
#define DX 300
#define DY 300
#define DZ 300
#define RNK  48
#define PSTR 64    // padded halves per plane cell (128 B, line-aligned)
#define NC   27

// fp16 planes (cell-major, 64-half padded rows), fp32 vectors (cell-major, 48 floats)
__device__ __align__(16) __half g_xyH[DX * DY * PSTR];
__device__ __align__(16) __half g_xzH[DX * DZ * PSTR];
__device__ __align__(16) __half g_yzH[DY * DZ * PSTR];
__device__ __align__(16) float  g_xvT[DX * RNK];
__device__ __align__(16) float  g_yvT[DY * RNK];
__device__ __align__(16) float  g_zvT[DZ * RNK];

typedef unsigned long long u64;

// ---------- packed f32x2 helpers ----------
__device__ __forceinline__ u64 pk2(float lo, float hi) {
    u64 r;
    asm("mov.b64 %0, {%1, %2};" : "=l"(r) : "f"(lo), "f"(hi));
    return r;
}
__device__ __forceinline__ void upk2(u64 v, float& lo, float& hi) {
    asm("mov.b64 {%0, %1}, %2;" : "=f"(lo), "=f"(hi) : "l"(v));
}
__device__ __forceinline__ u64 f2mul(u64 a, u64 b) {
    u64 d;
    asm("mul.rn.f32x2 %0, %1, %2;" : "=l"(d) : "l"(a), "l"(b));
    return d;
}
__device__ __forceinline__ u64 f2add(u64 a, u64 b) {
    u64 d;
    asm("add.rn.f32x2 %0, %1, %2;" : "=l"(d) : "l"(a), "l"(b));
    return d;
}
__device__ __forceinline__ u64 f2fma(u64 a, u64 b, u64 c) {
    u64 d;
    asm("fma.rn.f32x2 %0, %1, %2, %3;" : "=l"(d) : "l"(a), "l"(b), "l"(c));
    return d;
}
__device__ __forceinline__ u64 h2f2(unsigned int h) {
    float2 f = __half22float2(*(__half2*)&h);
    return pk2(f.x, f.y);
}

// ---------- merged transpose/convert: [RNK][cells] -> fp16 [cells][PSTR] (planes)
//                                                   -> fp32 [cells][RNK]  (vectors)
__global__ void __launch_bounds__(128) transpose_all(
    const float* __restrict__ xy, const float* __restrict__ xz,
    const float* __restrict__ yz, const float* __restrict__ xv,
    const float* __restrict__ yv, const float* __restrict__ zv)
{
    __shared__ float tile[RNK][129];
    int b = blockIdx.x;
    int t = threadIdx.x;

    if (b < 2112) {
        const float* src;
        __half* dst;
        int base;
        const int cells = DX * DY;     // 90000 for every plane
        if (b < 704)       { src = xy; dst = g_xyH; base = b * 128; }
        else if (b < 1408) { src = xz; dst = g_xzH; base = (b - 704) * 128; }
        else               { src = yz; dst = g_yzH; base = (b - 1408) * 128; }

        int nc = cells - base;
        if (nc > 128) nc = 128;

        #pragma unroll
        for (int r = 0; r < RNK; r++) {
            if (t < nc) tile[r][t] = src[r * cells + base + t];
        }
        __syncthreads();
        __half2* dst2 = (__half2*)dst;
        for (int i = t; i < nc * 32; i += 128) {   // 32 half2 per cell
            int cl = i >> 5;
            int p  = i & 31;
            float lo = (2 * p     < RNK) ? tile[2 * p][cl]     : 0.0f;
            float hi = (2 * p + 1 < RNK) ? tile[2 * p + 1][cl] : 0.0f;
            dst2[(u64)(base + cl) * 32 + p] = __floats2half2_rn(lo, hi);
        }
    } else {
        int vb = b - 2112;
        int vi = vb / 3;
        int base = (vb % 3) * 128;
        const int cells = DX;          // 300 for every vector
        const float* src = (vi == 0) ? xv : ((vi == 1) ? yv : zv);
        float* dst = (vi == 0) ? g_xvT : ((vi == 1) ? g_yvT : g_zvT);

        int nc = cells - base;
        if (nc > 128) nc = 128;
        if (nc <= 0) return;

        #pragma unroll
        for (int r = 0; r < RNK; r++) {
            if (t < nc) tile[r][t] = src[r * cells + base + t];
        }
        __syncthreads();
        for (int i = t; i < nc * RNK; i += 128) {
            int cl = i / RNK;
            int r  = i - cl * RNK;
            dst[(base + cl) * RNK + r] = tile[r][cl];
        }
    }
}

__device__ __forceinline__ void prep_coord(float g, int L, int& i0, int& i1, float& f)
{
    float t  = (g + 1.0f) * 0.5f;
    float ih = t * (float)(L - 1);
    int i = (int)floorf(ih);
    i = max(0, min(i, L - 1));
    i0 = i;
    i1 = min(i + 1, L - 1);
    f = ih - (float)i;
}

// one plane-corner gather for lane s: 16B (ranks 8s..8s+7) + 8B (ranks 32+4s..+3)
struct PC { uint4 a; uint2 b; };
__device__ __forceinline__ PC ldpc(const __half* cell, int s)
{
    PC r;
    r.a = *(const uint4*)((const char*)cell + s * 16);
    r.b = *(const uint2*)((const char*)cell + 64 + s * 8);
    return r;
}

// matvec: acc += f * Frow[0..27]
__device__ __forceinline__ void mv(const float* __restrict__ row, float f, u64* acc)
{
    u64 F2 = pk2(f, f);
    const ulonglong2* Fr = (const ulonglong2*)row;
    #pragma unroll
    for (int m = 0; m < 7; m++) {
        ulonglong2 q = Fr[m];
        acc[m * 2 + 0] = f2fma(F2, q.x, acc[m * 2 + 0]);
        acc[m * 2 + 1] = f2fma(F2, q.y, acc[m * 2 + 1]);
    }
}

// one segment: fp16 bilinear corners (already loaded) * fp32 vec lerp -> matvec
__device__ __forceinline__ void do_seg(
    const PC& c00, const PC& c01, const PC& c10, const PC& c11,
    const float* __restrict__ vbase0, const float* __restrict__ vbase1, int s,
    float fh, float fw, float fv,
    const float* __restrict__ sFseg, u64* acc)
{
    float w00 = (1.0f - fh) * (1.0f - fw);
    float w01 = (1.0f - fh) * fw;
    float w10 = fh * (1.0f - fw);
    float w11 = fh * fw;
    u64 W00 = pk2(w00, w00), W01 = pk2(w01, w01);
    u64 W10 = pk2(w10, w10), W11 = pk2(w11, w11);
    u64 FV  = pk2(fv, fv),  GV = pk2(1.0f - fv, 1.0f - fv);

    // vectors: chunkA ranks 8s..8s+7, chunkB ranks 32+4s..+3
    float4 u0 = *(const float4*)(vbase0 + 8 * s);
    float4 u1 = *(const float4*)(vbase0 + 8 * s + 4);
    float4 ub = *(const float4*)(vbase0 + 32 + 4 * s);
    float4 q0 = *(const float4*)(vbase1 + 8 * s);
    float4 q1 = *(const float4*)(vbase1 + 8 * s + 4);
    float4 qb = *(const float4*)(vbase1 + 32 + 4 * s);

    // ---- chunk A: 4 packed pairs (ranks 8s+2k, 8s+2k+1) ----
    const unsigned int* a00 = (const unsigned int*)&c00.a;
    const unsigned int* a01 = (const unsigned int*)&c01.a;
    const unsigned int* a10 = (const unsigned int*)&c10.a;
    const unsigned int* a11 = (const unsigned int*)&c11.a;
    u64 UA[4] = { pk2(u0.x, u0.y), pk2(u0.z, u0.w), pk2(u1.x, u1.y), pk2(u1.z, u1.w) };
    u64 QA[4] = { pk2(q0.x, q0.y), pk2(q0.z, q0.w), pk2(q1.x, q1.y), pk2(q1.z, q1.w) };

    #pragma unroll
    for (int k = 0; k < 4; k++) {
        u64 t = f2mul(W00, h2f2(a00[k]));
        t = f2fma(W01, h2f2(a01[k]), t);
        t = f2fma(W10, h2f2(a10[k]), t);
        t = f2fma(W11, h2f2(a11[k]), t);
        u64 v = f2fma(FV, QA[k], f2mul(GV, UA[k]));
        u64 fe = f2mul(t, v);
        float flo, fhi;
        upk2(fe, flo, fhi);
        // rows: e=2k -> slot 8k+s ; e=2k+1 -> slot 8k+4+s
        mv(sFseg + (8 * k + s) * 28, flo, acc);
        mv(sFseg + (8 * k + 4 + s) * 28, fhi, acc);
    }

    // ---- chunk B: 2 packed pairs (ranks 32+4s+2k, +2k+1) ----
    const unsigned int* b00 = (const unsigned int*)&c00.b;
    const unsigned int* b01 = (const unsigned int*)&c01.b;
    const unsigned int* b10 = (const unsigned int*)&c10.b;
    const unsigned int* b11 = (const unsigned int*)&c11.b;
    u64 UB[2] = { pk2(ub.x, ub.y), pk2(ub.z, ub.w) };
    u64 QB[2] = { pk2(qb.x, qb.y), pk2(qb.z, qb.w) };

    #pragma unroll
    for (int k = 0; k < 2; k++) {
        u64 t = f2mul(W00, h2f2(b00[k]));
        t = f2fma(W01, h2f2(b01[k]), t);
        t = f2fma(W10, h2f2(b10[k]), t);
        t = f2fma(W11, h2f2(b11[k]), t);
        u64 v = f2fma(FV, QB[k], f2mul(GV, UB[k]));
        u64 fe = f2mul(t, v);
        float flo, fhi;
        upk2(fe, flo, fhi);
        // rows: slot 32+8k+s and 36+8k+s
        mv(sFseg + (32 + 8 * k + s) * 28, flo, acc);
        mv(sFseg + (36 + 8 * k + s) * 28, fhi, acc);
    }
}

__global__ void __launch_bounds__(256, 2) sample_kernel(
    const float* __restrict__ xyz, const float* __restrict__ fvec,
    float* __restrict__ out)
{
    // sF: permuted padded F (144 x 28). Reused as output staging after matvec.
    __shared__ __align__(16) float sF[144 * 28];
    __shared__ float sXYZ[64 * 3];

    int tid  = threadIdx.x;
    int lane = tid & 31;
    int warp = tid >> 5;
    int s    = lane & 3;
    int pw   = lane >> 2;
    int pp   = warp * 8 + pw;
    int base = blockIdx.x * 64;

    // Permutation: within each 48-row segment block, rows rr<32 (chunkA, rr=8s+e)
    // go to slot 4e+s; rows rr>=32 (chunkB, rr=32+4s+e) go to slot 32+4e+s.
    for (int i = tid; i < 144 * 28; i += 256) {
        int r = i / 28;
        int c = i - r * 28;
        int seg = r / 48;
        int rr  = r - seg * 48;
        int slot;
        if (rr < 32) slot = seg * 48 + ((rr & 7) << 2) + (rr >> 3);
        else { int tb = rr - 32; slot = seg * 48 + 32 + ((tb & 3) << 2) + (tb >> 2); }
        sF[slot * 28 + c] = (c < NC) ? fvec[r * NC + c] : 0.0f;
    }
    if (tid < 192) sXYZ[tid] = xyz[base * 3 + tid];
    __syncthreads();

    float x = sXYZ[pp * 3 + 0];
    float y = sXYZ[pp * 3 + 1];
    float z = sXYZ[pp * 3 + 2];

    int ix0, ix1, iy0, iy1, iz0, iz1;
    float fx, fy, fz;
    prep_coord(x * 2.0f - 1.0f, DX, ix0, ix1, fx);
    prep_coord(y * 2.0f - 1.0f, DY, iy0, iy1, fy);
    prep_coord(z * 2.0f - 1.0f, DZ, iz0, iz1, fz);

    u64 acc[14];
    #pragma unroll
    for (int c = 0; c < 14; c++) acc[c] = 0ULL;

    // ---- software-pipelined gathers: load seg k+1 before computing seg k ----
    // seg0: xy plane
    PC c00 = ldpc(g_xyH + (u64)(ix0 * DY + iy0) * PSTR, s);
    PC c01 = ldpc(g_xyH + (u64)(ix0 * DY + iy1) * PSTR, s);
    PC c10 = ldpc(g_xyH + (u64)(ix1 * DY + iy0) * PSTR, s);
    PC c11 = ldpc(g_xyH + (u64)(ix1 * DY + iy1) * PSTR, s);

    // prefetch seg1: xz plane
    PC n00 = ldpc(g_xzH + (u64)(ix0 * DZ + iz0) * PSTR, s);
    PC n01 = ldpc(g_xzH + (u64)(ix0 * DZ + iz1) * PSTR, s);
    PC n10 = ldpc(g_xzH + (u64)(ix1 * DZ + iz0) * PSTR, s);
    PC n11 = ldpc(g_xzH + (u64)(ix1 * DZ + iz1) * PSTR, s);

    do_seg(c00, c01, c10, c11, g_zvT + iz0 * RNK, g_zvT + iz1 * RNK, s,
           fx, fy, fz, sF, acc);

    // prefetch seg2: yz plane
    c00 = ldpc(g_yzH + (u64)(iy0 * DZ + iz0) * PSTR, s);
    c01 = ldpc(g_yzH + (u64)(iy0 * DZ + iz1) * PSTR, s);
    c10 = ldpc(g_yzH + (u64)(iy1 * DZ + iz0) * PSTR, s);
    c11 = ldpc(g_yzH + (u64)(iy1 * DZ + iz1) * PSTR, s);

    do_seg(n00, n01, n10, n11, g_yvT + iy0 * RNK, g_yvT + iy1 * RNK, s,
           fx, fz, fy, sF + 48 * 28, acc);

    do_seg(c00, c01, c10, c11, g_xvT + ix0 * RNK, g_xvT + ix1 * RNK, s,
           fy, fz, fx, sF + 96 * 28, acc);

    // reduce across the 4 lanes of each point
    #pragma unroll
    for (int m = 0; m < 14; m++) {
        u64 t = __shfl_xor_sync(0xffffffffu, acc[m], 1);
        acc[m] = f2add(acc[m], t);
        t = __shfl_xor_sync(0xffffffffu, acc[m], 2);
        acc[m] = f2add(acc[m], t);
    }

    __syncthreads();   // all matvec reads of sF done; reuse as staging

    if (s == 0) {
        u64* dst = (u64*)(sF + pp * 28);
        #pragma unroll
        for (int m = 0; m < 14; m++) dst[m] = acc[m];  // slot 27 junk, never read
    }
    __syncthreads();

    #pragma unroll 2
    for (int i = tid; i < 64 * NC; i += 256) {
        int pt = i / NC;
        int c  = i - pt * NC;
        out[base * NC + i] = sF[pt * 28 + c];
    }
}

extern "C" void kernel_launch(void* const* d_in, const int* in_sizes, int n_in,
                              void* d_out, int out_size)
{
    const float* xyz = (const float*)d_in[0];
    const float* xyp = (const float*)d_in[1];
    const float* xzp = (const float*)d_in[2];
    const float* yzp = (const float*)d_in[3];
    const float* xv  = (const float*)d_in[4];
    const float* yv  = (const float*)d_in[5];
    const float* zv  = (const float*)d_in[6];
    const float* fv  = (const float*)d_in[7];
    float* out = (float*)d_out;

    transpose_all<<<2121, 128>>>(xyp, xzp, yzp, xv, yv, zv);
    sample_kernel<<<NPTS / 64, 256>>>(xyz, fv, out);
}

// round 7
// speedup vs baseline: 1.0007x; 1.0002x over previous
#include <cuda_runtime.h>
#include <cuda_fp16.h>

#define NPTS 1000000
#define DX 300
#define DY 300
#define DZ 300
#define RNK  48
#define PSTR 64    // padded halves per plane cell (128 B, line-aligned)
#define NC   27

// fp16 planes (cell-major, 64-half padded rows), fp32 vectors (cell-major, 48 floats)
__device__ __align__(16) __half g_xyH[DX * DY * PSTR];
__device__ __align__(16) __half g_xzH[DX * DZ * PSTR];
__device__ __align__(16) __half g_yzH[DY * DZ * PSTR];
__device__ __align__(16) float  g_xvT[DX * RNK];
__device__ __align__(16) float  g_yvT[DY * RNK];
__device__ __align__(16) float  g_zvT[DZ * RNK];

typedef unsigned long long u64;

// ---------- packed f32x2 helpers ----------
__device__ __forceinline__ u64 pk2(float lo, float hi) {
    u64 r;
    asm("mov.b64 %0, {%1, %2};" : "=l"(r) : "f"(lo), "f"(hi));
    return r;
}
__device__ __forceinline__ void upk2(u64 v, float& lo, float& hi) {
    asm("mov.b64 {%0, %1}, %2;" : "=f"(lo), "=f"(hi) : "l"(v));
}
__device__ __forceinline__ u64 f2mul(u64 a, u64 b) {
    u64 d;
    asm("mul.rn.f32x2 %0, %1, %2;" : "=l"(d) : "l"(a), "l"(b));
    return d;
}
__device__ __forceinline__ u64 f2add(u64 a, u64 b) {
    u64 d;
    asm("add.rn.f32x2 %0, %1, %2;" : "=l"(d) : "l"(a), "l"(b));
    return d;
}
__device__ __forceinline__ u64 f2fma(u64 a, u64 b, u64 c) {
    u64 d;
    asm("fma.rn.f32x2 %0, %1, %2, %3;" : "=l"(d) : "l"(a), "l"(b), "l"(c));
    return d;
}
__device__ __forceinline__ u64 h2f2(unsigned int h) {
    float2 f = __half22float2(*(__half2*)&h);
    return pk2(f.x, f.y);
}

// ---------- merged transpose/convert: [RNK][cells] -> fp16 [cells][PSTR] (planes)
//                                                   -> fp32 [cells][RNK]  (vectors)
__global__ void __launch_bounds__(128) transpose_all(
    const float* __restrict__ xy, const float* __restrict__ xz,
    const float* __restrict__ yz, const float* __restrict__ xv,
    const float* __restrict__ yv, const float* __restrict__ zv)
{
    __shared__ float tile[RNK][129];
    int b = blockIdx.x;
    int t = threadIdx.x;

    if (b < 2112) {
        const float* src;
        __half* dst;
        int base;
        const int cells = DX * DY;     // 90000 for every plane
        if (b < 704)       { src = xy; dst = g_xyH; base = b * 128; }
        else if (b < 1408) { src = xz; dst = g_xzH; base = (b - 704) * 128; }
        else               { src = yz; dst = g_yzH; base = (b - 1408) * 128; }

        int nc = cells - base;
        if (nc > 128) nc = 128;

        #pragma unroll
        for (int r = 0; r < RNK; r++) {
            if (t < nc) tile[r][t] = src[r * cells + base + t];
        }
        __syncthreads();
        __half2* dst2 = (__half2*)dst;
        for (int i = t; i < nc * 32; i += 128) {   // 32 half2 per cell
            int cl = i >> 5;
            int p  = i & 31;
            float lo = (2 * p     < RNK) ? tile[2 * p][cl]     : 0.0f;
            float hi = (2 * p + 1 < RNK) ? tile[2 * p + 1][cl] : 0.0f;
            dst2[(u64)(base + cl) * 32 + p] = __floats2half2_rn(lo, hi);
        }
    } else {
        int vb = b - 2112;
        int vi = vb / 3;
        int base = (vb % 3) * 128;
        const int cells = DX;          // 300 for every vector
        const float* src = (vi == 0) ? xv : ((vi == 1) ? yv : zv);
        float* dst = (vi == 0) ? g_xvT : ((vi == 1) ? g_yvT : g_zvT);

        int nc = cells - base;
        if (nc > 128) nc = 128;
        if (nc <= 0) return;

        #pragma unroll
        for (int r = 0; r < RNK; r++) {
            if (t < nc) tile[r][t] = src[r * cells + base + t];
        }
        __syncthreads();
        for (int i = t; i < nc * RNK; i += 128) {
            int cl = i / RNK;
            int r  = i - cl * RNK;
            dst[(base + cl) * RNK + r] = tile[r][cl];
        }
    }
}

__device__ __forceinline__ void prep_coord(float g, int L, int& i0, int& i1, float& f)
{
    float t  = (g + 1.0f) * 0.5f;
    float ih = t * (float)(L - 1);
    int i = (int)floorf(ih);
    i = max(0, min(i, L - 1));
    i0 = i;
    i1 = min(i + 1, L - 1);
    f = ih - (float)i;
}

// one plane-corner gather for lane s: 16B (ranks 8s..8s+7) + 8B (ranks 32+4s..+3)
struct PC { uint4 a; uint2 b; };
__device__ __forceinline__ PC ldpc(const __half* cell, int s)
{
    PC r;
    r.a = *(const uint4*)((const char*)cell + s * 16);
    r.b = *(const uint2*)((const char*)cell + 64 + s * 8);
    return r;
}

// matvec: acc += f * Frow[0..27]
__device__ __forceinline__ void mv(const float* __restrict__ row, float f, u64* acc)
{
    u64 F2 = pk2(f, f);
    const ulonglong2* Fr = (const ulonglong2*)row;
    #pragma unroll
    for (int m = 0; m < 7; m++) {
        ulonglong2 q = Fr[m];
        acc[m * 2 + 0] = f2fma(F2, q.x, acc[m * 2 + 0]);
        acc[m * 2 + 1] = f2fma(F2, q.y, acc[m * 2 + 1]);
    }
}

// one segment: fp16 bilinear corners (already loaded) * fp32 vec lerp -> matvec
__device__ __forceinline__ void do_seg(
    const PC& c00, const PC& c01, const PC& c10, const PC& c11,
    const float* __restrict__ vbase0, const float* __restrict__ vbase1, int s,
    float fh, float fw, float fv,
    const float* __restrict__ sFseg, u64* acc)
{
    float w00 = (1.0f - fh) * (1.0f - fw);
    float w01 = (1.0f - fh) * fw;
    float w10 = fh * (1.0f - fw);
    float w11 = fh * fw;
    u64 W00 = pk2(w00, w00), W01 = pk2(w01, w01);
    u64 W10 = pk2(w10, w10), W11 = pk2(w11, w11);
    u64 FV  = pk2(fv, fv),  GV = pk2(1.0f - fv, 1.0f - fv);

    // vectors: chunkA ranks 8s..8s+7, chunkB ranks 32+4s..+3
    float4 u0 = *(const float4*)(vbase0 + 8 * s);
    float4 u1 = *(const float4*)(vbase0 + 8 * s + 4);
    float4 ub = *(const float4*)(vbase0 + 32 + 4 * s);
    float4 q0 = *(const float4*)(vbase1 + 8 * s);
    float4 q1 = *(const float4*)(vbase1 + 8 * s + 4);
    float4 qb = *(const float4*)(vbase1 + 32 + 4 * s);

    // ---- chunk A: 4 packed pairs (ranks 8s+2k, 8s+2k+1) ----
    const unsigned int* a00 = (const unsigned int*)&c00.a;
    const unsigned int* a01 = (const unsigned int*)&c01.a;
    const unsigned int* a10 = (const unsigned int*)&c10.a;
    const unsigned int* a11 = (const unsigned int*)&c11.a;
    u64 UA[4] = { pk2(u0.x, u0.y), pk2(u0.z, u0.w), pk2(u1.x, u1.y), pk2(u1.z, u1.w) };
    u64 QA[4] = { pk2(q0.x, q0.y), pk2(q0.z, q0.w), pk2(q1.x, q1.y), pk2(q1.z, q1.w) };

    #pragma unroll
    for (int k = 0; k < 4; k++) {
        u64 t = f2mul(W00, h2f2(a00[k]));
        t = f2fma(W01, h2f2(a01[k]), t);
        t = f2fma(W10, h2f2(a10[k]), t);
        t = f2fma(W11, h2f2(a11[k]), t);
        u64 v = f2fma(FV, QA[k], f2mul(GV, UA[k]));
        u64 fe = f2mul(t, v);
        float flo, fhi;
        upk2(fe, flo, fhi);
        // rows: e=2k -> slot 8k+s ; e=2k+1 -> slot 8k+4+s
        mv(sFseg + (8 * k + s) * 28, flo, acc);
        mv(sFseg + (8 * k + 4 + s) * 28, fhi, acc);
    }

    // ---- chunk B: 2 packed pairs (ranks 32+4s+2k, +2k+1) ----
    const unsigned int* b00 = (const unsigned int*)&c00.b;
    const unsigned int* b01 = (const unsigned int*)&c01.b;
    const unsigned int* b10 = (const unsigned int*)&c10.b;
    const unsigned int* b11 = (const unsigned int*)&c11.b;
    u64 UB[2] = { pk2(ub.x, ub.y), pk2(ub.z, ub.w) };
    u64 QB[2] = { pk2(qb.x, qb.y), pk2(qb.z, qb.w) };

    #pragma unroll
    for (int k = 0; k < 2; k++) {
        u64 t = f2mul(W00, h2f2(b00[k]));
        t = f2fma(W01, h2f2(b01[k]), t);
        t = f2fma(W10, h2f2(b10[k]), t);
        t = f2fma(W11, h2f2(b11[k]), t);
        u64 v = f2fma(FV, QB[k], f2mul(GV, UB[k]));
        u64 fe = f2mul(t, v);
        float flo, fhi;
        upk2(fe, flo, fhi);
        // rows: slot 32+8k+s and 36+8k+s
        mv(sFseg + (32 + 8 * k + s) * 28, flo, acc);
        mv(sFseg + (36 + 8 * k + s) * 28, fhi, acc);
    }
}

__global__ void __launch_bounds__(256, 2) sample_kernel(
    const float* __restrict__ xyz, const float* __restrict__ fvec,
    float* __restrict__ out)
{
    // sF: permuted padded F (144 x 28). Reused as output staging after matvec.
    __shared__ __align__(16) float sF[144 * 28];
    __shared__ float sXYZ[64 * 3];

    int tid  = threadIdx.x;
    int lane = tid & 31;
    int warp = tid >> 5;
    int s    = lane & 3;
    int pw   = lane >> 2;
    int pp   = warp * 8 + pw;
    int base = blockIdx.x * 64;

    // Permutation: within each 48-row segment block, rows rr<32 (chunkA, rr=8s+e)
    // go to slot 4e+s; rows rr>=32 (chunkB, rr=32+4s+e) go to slot 32+4e+s.
    for (int i = tid; i < 144 * 28; i += 256) {
        int r = i / 28;
        int c = i - r * 28;
        int seg = r / 48;
        int rr  = r - seg * 48;
        int slot;
        if (rr < 32) slot = seg * 48 + ((rr & 7) << 2) + (rr >> 3);
        else { int tb = rr - 32; slot = seg * 48 + 32 + ((tb & 3) << 2) + (tb >> 2); }
        sF[slot * 28 + c] = (c < NC) ? fvec[r * NC + c] : 0.0f;
    }
    if (tid < 192) sXYZ[tid] = xyz[base * 3 + tid];
    __syncthreads();

    float x = sXYZ[pp * 3 + 0];
    float y = sXYZ[pp * 3 + 1];
    float z = sXYZ[pp * 3 + 2];

    int ix0, ix1, iy0, iy1, iz0, iz1;
    float fx, fy, fz;
    prep_coord(x * 2.0f - 1.0f, DX, ix0, ix1, fx);
    prep_coord(y * 2.0f - 1.0f, DY, iy0, iy1, fy);
    prep_coord(z * 2.0f - 1.0f, DZ, iz0, iz1, fz);

    u64 acc[14];
    #pragma unroll
    for (int c = 0; c < 14; c++) acc[c] = 0ULL;

    // ---- software-pipelined gathers: load seg k+1 before computing seg k ----
    // seg0: xy plane
    PC c00 = ldpc(g_xyH + (u64)(ix0 * DY + iy0) * PSTR, s);
    PC c01 = ldpc(g_xyH + (u64)(ix0 * DY + iy1) * PSTR, s);
    PC c10 = ldpc(g_xyH + (u64)(ix1 * DY + iy0) * PSTR, s);
    PC c11 = ldpc(g_xyH + (u64)(ix1 * DY + iy1) * PSTR, s);

    // prefetch seg1: xz plane
    PC n00 = ldpc(g_xzH + (u64)(ix0 * DZ + iz0) * PSTR, s);
    PC n01 = ldpc(g_xzH + (u64)(ix0 * DZ + iz1) * PSTR, s);
    PC n10 = ldpc(g_xzH + (u64)(ix1 * DZ + iz0) * PSTR, s);
    PC n11 = ldpc(g_xzH + (u64)(ix1 * DZ + iz1) * PSTR, s);

    do_seg(c00, c01, c10, c11, g_zvT + iz0 * RNK, g_zvT + iz1 * RNK, s,
           fx, fy, fz, sF, acc);

    // prefetch seg2: yz plane
    c00 = ldpc(g_yzH + (u64)(iy0 * DZ + iz0) * PSTR, s);
    c01 = ldpc(g_yzH + (u64)(iy0 * DZ + iz1) * PSTR, s);
    c10 = ldpc(g_yzH + (u64)(iy1 * DZ + iz0) * PSTR, s);
    c11 = ldpc(g_yzH + (u64)(iy1 * DZ + iz1) * PSTR, s);

    do_seg(n00, n01, n10, n11, g_yvT + iy0 * RNK, g_yvT + iy1 * RNK, s,
           fx, fz, fy, sF + 48 * 28, acc);

    do_seg(c00, c01, c10, c11, g_xvT + ix0 * RNK, g_xvT + ix1 * RNK, s,
           fy, fz, fx, sF + 96 * 28, acc);

    // reduce across the 4 lanes of each point
    #pragma unroll
    for (int m = 0; m < 14; m++) {
        u64 t = __shfl_xor_sync(0xffffffffu, acc[m], 1);
        acc[m] = f2add(acc[m], t);
        t = __shfl_xor_sync(0xffffffffu, acc[m], 2);
        acc[m] = f2add(acc[m], t);
    }

    __syncthreads();   // all matvec reads of sF done; reuse as staging

    if (s == 0) {
        u64* dst = (u64*)(sF + pp * 28);
        #pragma unroll
        for (int m = 0; m < 14; m++) dst[m] = acc[m];  // slot 27 junk, never read
    }
    __syncthreads();

    #pragma unroll 2
    for (int i = tid; i < 64 * NC; i += 256) {
        int pt = i / NC;
        int c  = i - pt * NC;
        out[base * NC + i] = sF[pt * 28 + c];
    }
}

extern "C" void kernel_launch(void* const* d_in, const int* in_sizes, int n_in,
                              void* d_out, int out_size)
{
    const float* xyz = (const float*)d_in[0];
    const float* xyp = (const float*)d_in[1];
    const float* xzp = (const float*)d_in[2];
    const float* yzp = (const float*)d_in[3];
    const float* xv  = (const float*)d_in[4];
    const float* yv  = (const float*)d_in[5];
    const float* zv  = (const float*)d_in[6];
    const float* fv  = (const float*)d_in[7];
    float* out = (float*)d_out;

    transpose_all<<<2121, 128>>>(xyp, xzp, yzp, xv, yv, zv);
    sample_kernel<<<NPTS / 64, 256>>>(xyz, fv, out);
}

// round 8
// speedup vs baseline: 1.0019x; 1.0012x over previous
#include <cuda_runtime.h>
#include <cuda_fp16.h>

#define NPTS 1000000
#define DX 300
#define DY 300
#define DZ 300
#define RNK  48
#define PSTR 64    // padded halves per plane cell (128 B, line-aligned)
#define NC   27

// fp16 planes (cell-major, 64-half padded rows), fp32 vectors (cell-major, 48 floats)
__device__ __align__(16) __half g_xyH[DX * DY * PSTR];
__device__ __align__(16) __half g_xzH[DX * DZ * PSTR];
__device__ __align__(16) __half g_yzH[DY * DZ * PSTR];
__device__ __align__(16) float  g_xvT[DX * RNK];
__device__ __align__(16) float  g_yvT[DY * RNK];
__device__ __align__(16) float  g_zvT[DZ * RNK];

typedef unsigned long long u64;

// ---------- packed f32x2 helpers ----------
__device__ __forceinline__ u64 pk2(float lo, float hi) {
    u64 r;
    asm("mov.b64 %0, {%1, %2};" : "=l"(r) : "f"(lo), "f"(hi));
    return r;
}
__device__ __forceinline__ void upk2(u64 v, float& lo, float& hi) {
    asm("mov.b64 {%0, %1}, %2;" : "=f"(lo), "=f"(hi) : "l"(v));
}
__device__ __forceinline__ u64 f2mul(u64 a, u64 b) {
    u64 d;
    asm("mul.rn.f32x2 %0, %1, %2;" : "=l"(d) : "l"(a), "l"(b));
    return d;
}
__device__ __forceinline__ u64 f2add(u64 a, u64 b) {
    u64 d;
    asm("add.rn.f32x2 %0, %1, %2;" : "=l"(d) : "l"(a), "l"(b));
    return d;
}
__device__ __forceinline__ u64 f2fma(u64 a, u64 b, u64 c) {
    u64 d;
    asm("fma.rn.f32x2 %0, %1, %2, %3;" : "=l"(d) : "l"(a), "l"(b), "l"(c));
    return d;
}
__device__ __forceinline__ u64 h2f2(unsigned int h) {
    float2 f = __half22float2(*(__half2*)&h);
    return pk2(f.x, f.y);
}

// ---------- merged transpose/convert: [RNK][cells] -> fp16 [cells][PSTR] (planes)
//                                                   -> fp32 [cells][RNK]  (vectors)
__global__ void __launch_bounds__(128) transpose_all(
    const float* __restrict__ xy, const float* __restrict__ xz,
    const float* __restrict__ yz, const float* __restrict__ xv,
    const float* __restrict__ yv, const float* __restrict__ zv)
{
    __shared__ float tile[RNK][129];
    int b = blockIdx.x;
    int t = threadIdx.x;

    if (b < 2112) {
        const float* src;
        __half* dst;
        int base;
        const int cells = DX * DY;     // 90000 for every plane
        if (b < 704)       { src = xy; dst = g_xyH; base = b * 128; }
        else if (b < 1408) { src = xz; dst = g_xzH; base = (b - 704) * 128; }
        else               { src = yz; dst = g_yzH; base = (b - 1408) * 128; }

        int nc = cells - base;
        if (nc > 128) nc = 128;

        #pragma unroll
        for (int r = 0; r < RNK; r++) {
            if (t < nc) tile[r][t] = src[r * cells + base + t];
        }
        __syncthreads();
        __half2* dst2 = (__half2*)dst;
        for (int i = t; i < nc * 32; i += 128) {   // 32 half2 per cell
            int cl = i >> 5;
            int p  = i & 31;
            float lo = (2 * p     < RNK) ? tile[2 * p][cl]     : 0.0f;
            float hi = (2 * p + 1 < RNK) ? tile[2 * p + 1][cl] : 0.0f;
            dst2[(u64)(base + cl) * 32 + p] = __floats2half2_rn(lo, hi);
        }
    } else {
        int vb = b - 2112;
        int vi = vb / 3;
        int base = (vb % 3) * 128;
        const int cells = DX;          // 300 for every vector
        const float* src = (vi == 0) ? xv : ((vi == 1) ? yv : zv);
        float* dst = (vi == 0) ? g_xvT : ((vi == 1) ? g_yvT : g_zvT);

        int nc = cells - base;
        if (nc > 128) nc = 128;
        if (nc <= 0) return;

        #pragma unroll
        for (int r = 0; r < RNK; r++) {
            if (t < nc) tile[r][t] = src[r * cells + base + t];
        }
        __syncthreads();
        for (int i = t; i < nc * RNK; i += 128) {
            int cl = i / RNK;
            int r  = i - cl * RNK;
            dst[(base + cl) * RNK + r] = tile[r][cl];
        }
    }
}

__device__ __forceinline__ void prep_coord(float g, int L, int& i0, int& i1, float& f)
{
    float t  = (g + 1.0f) * 0.5f;
    float ih = t * (float)(L - 1);
    int i = (int)floorf(ih);
    i = max(0, min(i, L - 1));
    i0 = i;
    i1 = min(i + 1, L - 1);
    f = ih - (float)i;
}

// one plane-corner gather for lane s: 16B (ranks 8s..8s+7) + 8B (ranks 32+4s..+3)
struct PC { uint4 a; uint2 b; };
__device__ __forceinline__ PC ldpc(const __half* cell, int s)
{
    PC r;
    r.a = *(const uint4*)((const char*)cell + s * 16);
    r.b = *(const uint2*)((const char*)cell + 64 + s * 8);
    return r;
}

// matvec: acc += f * Frow[0..27]
__device__ __forceinline__ void mv(const float* __restrict__ row, float f, u64* acc)
{
    u64 F2 = pk2(f, f);
    const ulonglong2* Fr = (const ulonglong2*)row;
    #pragma unroll
    for (int m = 0; m < 7; m++) {
        ulonglong2 q = Fr[m];
        acc[m * 2 + 0] = f2fma(F2, q.x, acc[m * 2 + 0]);
        acc[m * 2 + 1] = f2fma(F2, q.y, acc[m * 2 + 1]);
    }
}

// one segment: fp16 bilinear corners (already loaded) * fp32 vec lerp -> matvec
__device__ __forceinline__ void do_seg(
    const PC& c00, const PC& c01, const PC& c10, const PC& c11,
    const float* __restrict__ vbase0, const float* __restrict__ vbase1, int s,
    float fh, float fw, float fv,
    const float* __restrict__ sFseg, u64* acc)
{
    float w00 = (1.0f - fh) * (1.0f - fw);
    float w01 = (1.0f - fh) * fw;
    float w10 = fh * (1.0f - fw);
    float w11 = fh * fw;
    u64 W00 = pk2(w00, w00), W01 = pk2(w01, w01);
    u64 W10 = pk2(w10, w10), W11 = pk2(w11, w11);
    u64 FV  = pk2(fv, fv),  GV = pk2(1.0f - fv, 1.0f - fv);

    // vectors: chunkA ranks 8s..8s+7, chunkB ranks 32+4s..+3
    float4 u0 = *(const float4*)(vbase0 + 8 * s);
    float4 u1 = *(const float4*)(vbase0 + 8 * s + 4);
    float4 ub = *(const float4*)(vbase0 + 32 + 4 * s);
    float4 q0 = *(const float4*)(vbase1 + 8 * s);
    float4 q1 = *(const float4*)(vbase1 + 8 * s + 4);
    float4 qb = *(const float4*)(vbase1 + 32 + 4 * s);

    // ---- chunk A: 4 packed pairs (ranks 8s+2k, 8s+2k+1) ----
    const unsigned int* a00 = (const unsigned int*)&c00.a;
    const unsigned int* a01 = (const unsigned int*)&c01.a;
    const unsigned int* a10 = (const unsigned int*)&c10.a;
    const unsigned int* a11 = (const unsigned int*)&c11.a;
    u64 UA[4] = { pk2(u0.x, u0.y), pk2(u0.z, u0.w), pk2(u1.x, u1.y), pk2(u1.z, u1.w) };
    u64 QA[4] = { pk2(q0.x, q0.y), pk2(q0.z, q0.w), pk2(q1.x, q1.y), pk2(q1.z, q1.w) };

    #pragma unroll
    for (int k = 0; k < 4; k++) {
        u64 t = f2mul(W00, h2f2(a00[k]));
        t = f2fma(W01, h2f2(a01[k]), t);
        t = f2fma(W10, h2f2(a10[k]), t);
        t = f2fma(W11, h2f2(a11[k]), t);
        u64 v = f2fma(FV, QA[k], f2mul(GV, UA[k]));
        u64 fe = f2mul(t, v);
        float flo, fhi;
        upk2(fe, flo, fhi);
        // rows: e=2k -> slot 8k+s ; e=2k+1 -> slot 8k+4+s
        mv(sFseg + (8 * k + s) * 28, flo, acc);
        mv(sFseg + (8 * k + 4 + s) * 28, fhi, acc);
    }

    // ---- chunk B: 2 packed pairs (ranks 32+4s+2k, +2k+1) ----
    const unsigned int* b00 = (const unsigned int*)&c00.b;
    const unsigned int* b01 = (const unsigned int*)&c01.b;
    const unsigned int* b10 = (const unsigned int*)&c10.b;
    const unsigned int* b11 = (const unsigned int*)&c11.b;
    u64 UB[2] = { pk2(ub.x, ub.y), pk2(ub.z, ub.w) };
    u64 QB[2] = { pk2(qb.x, qb.y), pk2(qb.z, qb.w) };

    #pragma unroll
    for (int k = 0; k < 2; k++) {
        u64 t = f2mul(W00, h2f2(b00[k]));
        t = f2fma(W01, h2f2(b01[k]), t);
        t = f2fma(W10, h2f2(b10[k]), t);
        t = f2fma(W11, h2f2(b11[k]), t);
        u64 v = f2fma(FV, QB[k], f2mul(GV, UB[k]));
        u64 fe = f2mul(t, v);
        float flo, fhi;
        upk2(fe, flo, fhi);
        // rows: slot 32+8k+s and 36+8k+s
        mv(sFseg + (32 + 8 * k + s) * 28, flo, acc);
        mv(sFseg + (36 + 8 * k + s) * 28, fhi, acc);
    }
}

__global__ void __launch_bounds__(256, 2) sample_kernel(
    const float* __restrict__ xyz, const float* __restrict__ fvec,
    float* __restrict__ out)
{
    // sF: permuted padded F (144 x 28). Reused as output staging after matvec.
    __shared__ __align__(16) float sF[144 * 28];
    __shared__ float sXYZ[64 * 3];

    int tid  = threadIdx.x;
    int lane = tid & 31;
    int warp = tid >> 5;
    int s    = lane & 3;
    int pw   = lane >> 2;
    int pp   = warp * 8 + pw;
    int base = blockIdx.x * 64;

    // Permutation: within each 48-row segment block, rows rr<32 (chunkA, rr=8s+e)
    // go to slot 4e+s; rows rr>=32 (chunkB, rr=32+4s+e) go to slot 32+4e+s.
    for (int i = tid; i < 144 * 28; i += 256) {
        int r = i / 28;
        int c = i - r * 28;
        int seg = r / 48;
        int rr  = r - seg * 48;
        int slot;
        if (rr < 32) slot = seg * 48 + ((rr & 7) << 2) + (rr >> 3);
        else { int tb = rr - 32; slot = seg * 48 + 32 + ((tb & 3) << 2) + (tb >> 2); }
        sF[slot * 28 + c] = (c < NC) ? fvec[r * NC + c] : 0.0f;
    }
    if (tid < 192) sXYZ[tid] = xyz[base * 3 + tid];
    __syncthreads();

    float x = sXYZ[pp * 3 + 0];
    float y = sXYZ[pp * 3 + 1];
    float z = sXYZ[pp * 3 + 2];

    int ix0, ix1, iy0, iy1, iz0, iz1;
    float fx, fy, fz;
    prep_coord(x * 2.0f - 1.0f, DX, ix0, ix1, fx);
    prep_coord(y * 2.0f - 1.0f, DY, iy0, iy1, fy);
    prep_coord(z * 2.0f - 1.0f, DZ, iz0, iz1, fz);

    u64 acc[14];
    #pragma unroll
    for (int c = 0; c < 14; c++) acc[c] = 0ULL;

    // ---- software-pipelined gathers: load seg k+1 before computing seg k ----
    // seg0: xy plane
    PC c00 = ldpc(g_xyH + (u64)(ix0 * DY + iy0) * PSTR, s);
    PC c01 = ldpc(g_xyH + (u64)(ix0 * DY + iy1) * PSTR, s);
    PC c10 = ldpc(g_xyH + (u64)(ix1 * DY + iy0) * PSTR, s);
    PC c11 = ldpc(g_xyH + (u64)(ix1 * DY + iy1) * PSTR, s);

    // prefetch seg1: xz plane
    PC n00 = ldpc(g_xzH + (u64)(ix0 * DZ + iz0) * PSTR, s);
    PC n01 = ldpc(g_xzH + (u64)(ix0 * DZ + iz1) * PSTR, s);
    PC n10 = ldpc(g_xzH + (u64)(ix1 * DZ + iz0) * PSTR, s);
    PC n11 = ldpc(g_xzH + (u64)(ix1 * DZ + iz1) * PSTR, s);

    do_seg(c00, c01, c10, c11, g_zvT + iz0 * RNK, g_zvT + iz1 * RNK, s,
           fx, fy, fz, sF, acc);

    // prefetch seg2: yz plane
    c00 = ldpc(g_yzH + (u64)(iy0 * DZ + iz0) * PSTR, s);
    c01 = ldpc(g_yzH + (u64)(iy0 * DZ + iz1) * PSTR, s);
    c10 = ldpc(g_yzH + (u64)(iy1 * DZ + iz0) * PSTR, s);
    c11 = ldpc(g_yzH + (u64)(iy1 * DZ + iz1) * PSTR, s);

    do_seg(n00, n01, n10, n11, g_yvT + iy0 * RNK, g_yvT + iy1 * RNK, s,
           fx, fz, fy, sF + 48 * 28, acc);

    do_seg(c00, c01, c10, c11, g_xvT + ix0 * RNK, g_xvT + ix1 * RNK, s,
           fy, fz, fx, sF + 96 * 28, acc);

    // reduce across the 4 lanes of each point
    #pragma unroll
    for (int m = 0; m < 14; m++) {
        u64 t = __shfl_xor_sync(0xffffffffu, acc[m], 1);
        acc[m] = f2add(acc[m], t);
        t = __shfl_xor_sync(0xffffffffu, acc[m], 2);
        acc[m] = f2add(acc[m], t);
    }

    __syncthreads();   // all matvec reads of sF done; reuse as staging

    if (s == 0) {
        u64* dst = (u64*)(sF + pp * 28);
        #pragma unroll
        for (int m = 0; m < 14; m++) dst[m] = acc[m];  // slot 27 junk, never read
    }
    __syncthreads();

    #pragma unroll 2
    for (int i = tid; i < 64 * NC; i += 256) {
        int pt = i / NC;
        int c  = i - pt * NC;
        out[base * NC + i] = sF[pt * 28 + c];
    }
}

extern "C" void kernel_launch(void* const* d_in, const int* in_sizes, int n_in,
                              void* d_out, int out_size)
{
    const float* xyz = (const float*)d_in[0];
    const float* xyp = (const float*)d_in[1];
    const float* xzp = (const float*)d_in[2];
    const float* yzp = (const float*)d_in[3];
    const float* xv  = (const float*)d_in[4];
    const float* yv  = (const float*)d_in[5];
    const float* zv  = (const float*)d_in[6];
    const float* fv  = (const float*)d_in[7];
    float* out = (float*)d_out;

    transpose_all<<<2121, 128>>>(xyp, xzp, yzp, xv, yv, zv);
    sample_kernel<<<NPTS / 64, 256>>>(xyz, fv, out);
}

// round 9
// speedup vs baseline: 1.0022x; 1.0003x over previous
#include <cuda_runtime.h>
#include <cuda_fp16.h>

#define NPTS 1000000
#define DX 300
#define DY 300
#define DZ 300
#define RNK  48
#define PSTR 64    // padded halves per plane cell (128 B, line-aligned)
#define NC   27

// fp16 planes (cell-major, 64-half padded rows), fp32 vectors (cell-major, 48 floats)
__device__ __align__(16) __half g_xyH[DX * DY * PSTR];
__device__ __align__(16) __half g_xzH[DX * DZ * PSTR];
__device__ __align__(16) __half g_yzH[DY * DZ * PSTR];
__device__ __align__(16) float  g_xvT[DX * RNK];
__device__ __align__(16) float  g_yvT[DY * RNK];
__device__ __align__(16) float  g_zvT[DZ * RNK];

typedef unsigned long long u64;

// ---------- packed f32x2 helpers ----------
__device__ __forceinline__ u64 pk2(float lo, float hi) {
    u64 r;
    asm("mov.b64 %0, {%1, %2};" : "=l"(r) : "f"(lo), "f"(hi));
    return r;
}
__device__ __forceinline__ void upk2(u64 v, float& lo, float& hi) {
    asm("mov.b64 {%0, %1}, %2;" : "=f"(lo), "=f"(hi) : "l"(v));
}
__device__ __forceinline__ u64 f2mul(u64 a, u64 b) {
    u64 d;
    asm("mul.rn.f32x2 %0, %1, %2;" : "=l"(d) : "l"(a), "l"(b));
    return d;
}
__device__ __forceinline__ u64 f2add(u64 a, u64 b) {
    u64 d;
    asm("add.rn.f32x2 %0, %1, %2;" : "=l"(d) : "l"(a), "l"(b));
    return d;
}
__device__ __forceinline__ u64 f2fma(u64 a, u64 b, u64 c) {
    u64 d;
    asm("fma.rn.f32x2 %0, %1, %2, %3;" : "=l"(d) : "l"(a), "l"(b), "l"(c));
    return d;
}
__device__ __forceinline__ u64 h2f2(unsigned int h) {
    float2 f = __half22float2(*(__half2*)&h);
    return pk2(f.x, f.y);
}

// ---------- merged transpose/convert: [RNK][cells] -> fp16 [cells][PSTR] (planes)
//                                                   -> fp32 [cells][RNK]  (vectors)
__global__ void __launch_bounds__(128) transpose_all(
    const float* __restrict__ xy, const float* __restrict__ xz,
    const float* __restrict__ yz, const float* __restrict__ xv,
    const float* __restrict__ yv, const float* __restrict__ zv)
{
    __shared__ float tile[RNK][129];
    int b = blockIdx.x;
    int t = threadIdx.x;

    if (b < 2112) {
        const float* src;
        __half* dst;
        int base;
        const int cells = DX * DY;     // 90000 for every plane
        if (b < 704)       { src = xy; dst = g_xyH; base = b * 128; }
        else if (b < 1408) { src = xz; dst = g_xzH; base = (b - 704) * 128; }
        else               { src = yz; dst = g_yzH; base = (b - 1408) * 128; }

        int nc = cells - base;
        if (nc > 128) nc = 128;

        #pragma unroll
        for (int r = 0; r < RNK; r++) {
            if (t < nc) tile[r][t] = src[r * cells + base + t];
        }
        __syncthreads();
        __half2* dst2 = (__half2*)dst;
        for (int i = t; i < nc * 32; i += 128) {   // 32 half2 per cell
            int cl = i >> 5;
            int p  = i & 31;
            float lo = (2 * p     < RNK) ? tile[2 * p][cl]     : 0.0f;
            float hi = (2 * p + 1 < RNK) ? tile[2 * p + 1][cl] : 0.0f;
            dst2[(u64)(base + cl) * 32 + p] = __floats2half2_rn(lo, hi);
        }
    } else {
        int vb = b - 2112;
        int vi = vb / 3;
        int base = (vb % 3) * 128;
        const int cells = DX;          // 300 for every vector
        const float* src = (vi == 0) ? xv : ((vi == 1) ? yv : zv);
        float* dst = (vi == 0) ? g_xvT : ((vi == 1) ? g_yvT : g_zvT);

        int nc = cells - base;
        if (nc > 128) nc = 128;
        if (nc <= 0) return;

        #pragma unroll
        for (int r = 0; r < RNK; r++) {
            if (t < nc) tile[r][t] = src[r * cells + base + t];
        }
        __syncthreads();
        for (int i = t; i < nc * RNK; i += 128) {
            int cl = i / RNK;
            int r  = i - cl * RNK;
            dst[(base + cl) * RNK + r] = tile[r][cl];
        }
    }
}

__device__ __forceinline__ void prep_coord(float g, int L, int& i0, int& i1, float& f)
{
    float t  = (g + 1.0f) * 0.5f;
    float ih = t * (float)(L - 1);
    int i = (int)floorf(ih);
    i = max(0, min(i, L - 1));
    i0 = i;
    i1 = min(i + 1, L - 1);
    f = ih - (float)i;
}

// one plane-corner gather for lane s: 16B (ranks 8s..8s+7) + 8B (ranks 32+4s..+3)
struct PC { uint4 a; uint2 b; };
__device__ __forceinline__ PC ldpc(const __half* cell, int s)
{
    PC r;
    r.a = *(const uint4*)((const char*)cell + s * 16);
    r.b = *(const uint2*)((const char*)cell + 64 + s * 8);
    return r;
}

// matvec: acc += f * Frow[0..27]
__device__ __forceinline__ void mv(const float* __restrict__ row, float f, u64* acc)
{
    u64 F2 = pk2(f, f);
    const ulonglong2* Fr = (const ulonglong2*)row;
    #pragma unroll
    for (int m = 0; m < 7; m++) {
        ulonglong2 q = Fr[m];
        acc[m * 2 + 0] = f2fma(F2, q.x, acc[m * 2 + 0]);
        acc[m * 2 + 1] = f2fma(F2, q.y, acc[m * 2 + 1]);
    }
}

// one segment: fp16 bilinear corners (already loaded) * fp32 vec lerp -> matvec
__device__ __forceinline__ void do_seg(
    const PC& c00, const PC& c01, const PC& c10, const PC& c11,
    const float* __restrict__ vbase0, const float* __restrict__ vbase1, int s,
    float fh, float fw, float fv,
    const float* __restrict__ sFseg, u64* acc)
{
    float w00 = (1.0f - fh) * (1.0f - fw);
    float w01 = (1.0f - fh) * fw;
    float w10 = fh * (1.0f - fw);
    float w11 = fh * fw;
    u64 W00 = pk2(w00, w00), W01 = pk2(w01, w01);
    u64 W10 = pk2(w10, w10), W11 = pk2(w11, w11);
    u64 FV  = pk2(fv, fv),  GV = pk2(1.0f - fv, 1.0f - fv);

    // vectors: chunkA ranks 8s..8s+7, chunkB ranks 32+4s..+3
    float4 u0 = *(const float4*)(vbase0 + 8 * s);
    float4 u1 = *(const float4*)(vbase0 + 8 * s + 4);
    float4 ub = *(const float4*)(vbase0 + 32 + 4 * s);
    float4 q0 = *(const float4*)(vbase1 + 8 * s);
    float4 q1 = *(const float4*)(vbase1 + 8 * s + 4);
    float4 qb = *(const float4*)(vbase1 + 32 + 4 * s);

    // ---- chunk A: 4 packed pairs (ranks 8s+2k, 8s+2k+1) ----
    const unsigned int* a00 = (const unsigned int*)&c00.a;
    const unsigned int* a01 = (const unsigned int*)&c01.a;
    const unsigned int* a10 = (const unsigned int*)&c10.a;
    const unsigned int* a11 = (const unsigned int*)&c11.a;
    u64 UA[4] = { pk2(u0.x, u0.y), pk2(u0.z, u0.w), pk2(u1.x, u1.y), pk2(u1.z, u1.w) };
    u64 QA[4] = { pk2(q0.x, q0.y), pk2(q0.z, q0.w), pk2(q1.x, q1.y), pk2(q1.z, q1.w) };

    #pragma unroll
    for (int k = 0; k < 4; k++) {
        u64 t = f2mul(W00, h2f2(a00[k]));
        t = f2fma(W01, h2f2(a01[k]), t);
        t = f2fma(W10, h2f2(a10[k]), t);
        t = f2fma(W11, h2f2(a11[k]), t);
        u64 v = f2fma(FV, QA[k], f2mul(GV, UA[k]));
        u64 fe = f2mul(t, v);
        float flo, fhi;
        upk2(fe, flo, fhi);
        // rows: e=2k -> slot 8k+s ; e=2k+1 -> slot 8k+4+s
        mv(sFseg + (8 * k + s) * 28, flo, acc);
        mv(sFseg + (8 * k + 4 + s) * 28, fhi, acc);
    }

    // ---- chunk B: 2 packed pairs (ranks 32+4s+2k, +2k+1) ----
    const unsigned int* b00 = (const unsigned int*)&c00.b;
    const unsigned int* b01 = (const unsigned int*)&c01.b;
    const unsigned int* b10 = (const unsigned int*)&c10.b;
    const unsigned int* b11 = (const unsigned int*)&c11.b;
    u64 UB[2] = { pk2(ub.x, ub.y), pk2(ub.z, ub.w) };
    u64 QB[2] = { pk2(qb.x, qb.y), pk2(qb.z, qb.w) };

    #pragma unroll
    for (int k = 0; k < 2; k++) {
        u64 t = f2mul(W00, h2f2(b00[k]));
        t = f2fma(W01, h2f2(b01[k]), t);
        t = f2fma(W10, h2f2(b10[k]), t);
        t = f2fma(W11, h2f2(b11[k]), t);
        u64 v = f2fma(FV, QB[k], f2mul(GV, UB[k]));
        u64 fe = f2mul(t, v);
        float flo, fhi;
        upk2(fe, flo, fhi);
        // rows: slot 32+8k+s and 36+8k+s
        mv(sFseg + (32 + 8 * k + s) * 28, flo, acc);
        mv(sFseg + (36 + 8 * k + s) * 28, fhi, acc);
    }
}

__global__ void __launch_bounds__(256, 2) sample_kernel(
    const float* __restrict__ xyz, const float* __restrict__ fvec,
    float* __restrict__ out)
{
    // sF: permuted padded F (144 x 28). Reused as output staging after matvec.
    __shared__ __align__(16) float sF[144 * 28];
    __shared__ float sXYZ[64 * 3];

    int tid  = threadIdx.x;
    int lane = tid & 31;
    int warp = tid >> 5;
    int s    = lane & 3;
    int pw   = lane >> 2;
    int pp   = warp * 8 + pw;
    int base = blockIdx.x * 64;

    // Permutation: within each 48-row segment block, rows rr<32 (chunkA, rr=8s+e)
    // go to slot 4e+s; rows rr>=32 (chunkB, rr=32+4s+e) go to slot 32+4e+s.
    for (int i = tid; i < 144 * 28; i += 256) {
        int r = i / 28;
        int c = i - r * 28;
        int seg = r / 48;
        int rr  = r - seg * 48;
        int slot;
        if (rr < 32) slot = seg * 48 + ((rr & 7) << 2) + (rr >> 3);
        else { int tb = rr - 32; slot = seg * 48 + 32 + ((tb & 3) << 2) + (tb >> 2); }
        sF[slot * 28 + c] = (c < NC) ? fvec[r * NC + c] : 0.0f;
    }
    if (tid < 192) sXYZ[tid] = xyz[base * 3 + tid];
    __syncthreads();

    float x = sXYZ[pp * 3 + 0];
    float y = sXYZ[pp * 3 + 1];
    float z = sXYZ[pp * 3 + 2];

    int ix0, ix1, iy0, iy1, iz0, iz1;
    float fx, fy, fz;
    prep_coord(x * 2.0f - 1.0f, DX, ix0, ix1, fx);
    prep_coord(y * 2.0f - 1.0f, DY, iy0, iy1, fy);
    prep_coord(z * 2.0f - 1.0f, DZ, iz0, iz1, fz);

    u64 acc[14];
    #pragma unroll
    for (int c = 0; c < 14; c++) acc[c] = 0ULL;

    // ---- software-pipelined gathers: load seg k+1 before computing seg k ----
    // seg0: xy plane
    PC c00 = ldpc(g_xyH + (u64)(ix0 * DY + iy0) * PSTR, s);
    PC c01 = ldpc(g_xyH + (u64)(ix0 * DY + iy1) * PSTR, s);
    PC c10 = ldpc(g_xyH + (u64)(ix1 * DY + iy0) * PSTR, s);
    PC c11 = ldpc(g_xyH + (u64)(ix1 * DY + iy1) * PSTR, s);

    // prefetch seg1: xz plane
    PC n00 = ldpc(g_xzH + (u64)(ix0 * DZ + iz0) * PSTR, s);
    PC n01 = ldpc(g_xzH + (u64)(ix0 * DZ + iz1) * PSTR, s);
    PC n10 = ldpc(g_xzH + (u64)(ix1 * DZ + iz0) * PSTR, s);
    PC n11 = ldpc(g_xzH + (u64)(ix1 * DZ + iz1) * PSTR, s);

    do_seg(c00, c01, c10, c11, g_zvT + iz0 * RNK, g_zvT + iz1 * RNK, s,
           fx, fy, fz, sF, acc);

    // prefetch seg2: yz plane
    c00 = ldpc(g_yzH + (u64)(iy0 * DZ + iz0) * PSTR, s);
    c01 = ldpc(g_yzH + (u64)(iy0 * DZ + iz1) * PSTR, s);
    c10 = ldpc(g_yzH + (u64)(iy1 * DZ + iz0) * PSTR, s);
    c11 = ldpc(g_yzH + (u64)(iy1 * DZ + iz1) * PSTR, s);

    do_seg(n00, n01, n10, n11, g_yvT + iy0 * RNK, g_yvT + iy1 * RNK, s,
           fx, fz, fy, sF + 48 * 28, acc);

    do_seg(c00, c01, c10, c11, g_xvT + ix0 * RNK, g_xvT + ix1 * RNK, s,
           fy, fz, fx, sF + 96 * 28, acc);

    // reduce across the 4 lanes of each point
    #pragma unroll
    for (int m = 0; m < 14; m++) {
        u64 t = __shfl_xor_sync(0xffffffffu, acc[m], 1);
        acc[m] = f2add(acc[m], t);
        t = __shfl_xor_sync(0xffffffffu, acc[m], 2);
        acc[m] = f2add(acc[m], t);
    }

    __syncthreads();   // all matvec reads of sF done; reuse as staging

    if (s == 0) {
        u64* dst = (u64*)(sF + pp * 28);
        #pragma unroll
        for (int m = 0; m < 14; m++) dst[m] = acc[m];  // slot 27 junk, never read
    }
    __syncthreads();

    #pragma unroll 2
    for (int i = tid; i < 64 * NC; i += 256) {
        int pt = i / NC;
        int c  = i - pt * NC;
        out[base * NC + i] = sF[pt * 28 + c];
    }
}

extern "C" void kernel_launch(void* const* d_in, const int* in_sizes, int n_in,
                              void* d_out, int out_size)
{
    const float* xyz = (const float*)d_in[0];
    const float* xyp = (const float*)d_in[1];
    const float* xzp = (const float*)d_in[2];
    const float* yzp = (const float*)d_in[3];
    const float* xv  = (const float*)d_in[4];
    const float* yv  = (const float*)d_in[5];
    const float* zv  = (const float*)d_in[6];
    const float* fv  = (const float*)d_in[7];
    float* out = (float*)d_out;

    transpose_all<<<2121, 128>>>(xyp, xzp, yzp, xv, yv, zv);
    sample_kernel<<<NPTS / 64, 256>>>(xyz, fv, out);
}

// round 11
// speedup vs baseline: 2.3396x; 2.3345x over previous
#include <cuda_runtime.h>
#include <cuda_fp16.h>
#include <cstdint>

#define NPTS 1000000
#define DX 300
#define DY 300
#define DZ 300
#define RNK  48
#define PSTR 64    // padded halves per plane cell (128 B, line-aligned)
#define NC   27

// fp16 planes (cell-major, 64-half padded rows), fp32 vectors (cell-major, 48 floats)
__device__ __align__(16) __half g_xyH[DX * DY * PSTR];
__device__ __align__(16) __half g_xzH[DX * DZ * PSTR];
__device__ __align__(16) __half g_yzH[DY * DZ * PSTR];
__device__ __align__(16) float  g_xvT[DX * RNK];
__device__ __align__(16) float  g_yvT[DY * RNK];
__device__ __align__(16) float  g_zvT[DZ * RNK];

typedef unsigned long long u64;

// ---------- smem layout (dynamic, bytes) ----------
// A: fe tile [128 pts][152 halves]  (stride 304 B, ldmatrix conflict-free)
// B: F tile  [144 k  ][40 halves]   (stride 80 B, ldmatrix conflict-free; cols 27..31 = 0)
// stage (reuses A): [128 pts][36 f32]
#define ASTR 152
#define BSTR 40
#define OFF_A    0
#define OFF_B    (128 * ASTR * 2)                 // 38912
#define OFF_XYZ  (OFF_B + 144 * BSTR * 2)         // 50432
#define SMEM_TOT (OFF_XYZ + 128 * 3 * 4)          // 51968

// ---------- packed f32x2 helpers ----------
__device__ __forceinline__ u64 pk2(float lo, float hi) {
    u64 r;
    asm("mov.b64 %0, {%1, %2};" : "=l"(r) : "f"(lo), "f"(hi));
    return r;
}
__device__ __forceinline__ void upk2(u64 v, float& lo, float& hi) {
    asm("mov.b64 {%0, %1}, %2;" : "=f"(lo), "=f"(hi) : "l"(v));
}
__device__ __forceinline__ u64 f2mul(u64 a, u64 b) {
    u64 d;
    asm("mul.rn.f32x2 %0, %1, %2;" : "=l"(d) : "l"(a), "l"(b));
    return d;
}
__device__ __forceinline__ u64 f2fma(u64 a, u64 b, u64 c) {
    u64 d;
    asm("fma.rn.f32x2 %0, %1, %2, %3;" : "=l"(d) : "l"(a), "l"(b), "l"(c));
    return d;
}
__device__ __forceinline__ u64 h2f2(unsigned int h) {
    float2 f = __half22float2(*(__half2*)&h);
    return pk2(f.x, f.y);
}
__device__ __forceinline__ uint32_t smem_u32(const void* p) {
    uint32_t a;
    asm("{ .reg .u64 t; cvta.to.shared.u64 t, %1; cvt.u32.u64 %0, t; }" : "=r"(a) : "l"(p));
    return a;
}

// ---------- ldmatrix / mma.sync ----------
__device__ __forceinline__ void ldsm_x4(uint32_t addr, uint32_t r[4]) {
    asm volatile("ldmatrix.sync.aligned.m8n8.x4.shared.b16 {%0,%1,%2,%3}, [%4];"
                 : "=r"(r[0]), "=r"(r[1]), "=r"(r[2]), "=r"(r[3]) : "r"(addr));
}
__device__ __forceinline__ void ldsm_x4_t(uint32_t addr, uint32_t r[4]) {
    asm volatile("ldmatrix.sync.aligned.m8n8.x4.trans.shared.b16 {%0,%1,%2,%3}, [%4];"
                 : "=r"(r[0]), "=r"(r[1]), "=r"(r[2]), "=r"(r[3]) : "r"(addr));
}
__device__ __forceinline__ void mma16816(float d[4], const uint32_t a[4],
                                         uint32_t b0, uint32_t b1) {
    asm volatile(
        "mma.sync.aligned.m16n8k16.row.col.f32.f16.f16.f32 "
        "{%0,%1,%2,%3}, {%4,%5,%6,%7}, {%8,%9}, {%0,%1,%2,%3};"
        : "+f"(d[0]), "+f"(d[1]), "+f"(d[2]), "+f"(d[3])
        : "r"(a[0]), "r"(a[1]), "r"(a[2]), "r"(a[3]), "r"(b0), "r"(b1));
}

// ---------- merged transpose/convert (unchanged) ----------
__global__ void __launch_bounds__(128) transpose_all(
    const float* __restrict__ xy, const float* __restrict__ xz,
    const float* __restrict__ yz, const float* __restrict__ xv,
    const float* __restrict__ yv, const float* __restrict__ zv)
{
    __shared__ float tile[RNK][129];
    int b = blockIdx.x;
    int t = threadIdx.x;

    if (b < 2112) {
        const float* src;
        __half* dst;
        int base;
        const int cells = DX * DY;
        if (b < 704)       { src = xy; dst = g_xyH; base = b * 128; }
        else if (b < 1408) { src = xz; dst = g_xzH; base = (b - 704) * 128; }
        else               { src = yz; dst = g_yzH; base = (b - 1408) * 128; }

        int nc = cells - base;
        if (nc > 128) nc = 128;

        #pragma unroll
        for (int r = 0; r < RNK; r++) {
            if (t < nc) tile[r][t] = src[r * cells + base + t];
        }
        __syncthreads();
        __half2* dst2 = (__half2*)dst;
        for (int i = t; i < nc * 32; i += 128) {
            int cl = i >> 5;
            int p  = i & 31;
            float lo = (2 * p     < RNK) ? tile[2 * p][cl]     : 0.0f;
            float hi = (2 * p + 1 < RNK) ? tile[2 * p + 1][cl] : 0.0f;
            dst2[(u64)(base + cl) * 32 + p] = __floats2half2_rn(lo, hi);
        }
    } else {
        int vb = b - 2112;
        int vi = vb / 3;
        int base = (vb % 3) * 128;
        const int cells = DX;
        const float* src = (vi == 0) ? xv : ((vi == 1) ? yv : zv);
        float* dst = (vi == 0) ? g_xvT : ((vi == 1) ? g_yvT : g_zvT);

        int nc = cells - base;
        if (nc > 128) nc = 128;
        if (nc <= 0) return;

        #pragma unroll
        for (int r = 0; r < RNK; r++) {
            if (t < nc) tile[r][t] = src[r * cells + base + t];
        }
        __syncthreads();
        for (int i = t; i < nc * RNK; i += 128) {
            int cl = i / RNK;
            int r  = i - cl * RNK;
            dst[(base + cl) * RNK + r] = tile[r][cl];
        }
    }
}

__device__ __forceinline__ void prep_coord(float g, int L, int& i0, int& i1, float& f)
{
    float t  = (g + 1.0f) * 0.5f;
    float ih = t * (float)(L - 1);
    int i = (int)floorf(ih);
    i = max(0, min(i, L - 1));
    i0 = i;
    i1 = min(i + 1, L - 1);
    f = ih - (float)i;
}

// one plane-corner gather for lane s: 16B (ranks 8s..8s+7) + 8B (ranks 32+4s..+3)
struct PC { uint4 a; uint2 b; };
__device__ __forceinline__ PC ldpc(const __half* cell, int s)
{
    PC r;
    r.a = *(const uint4*)((const char*)cell + s * 16);
    r.b = *(const uint2*)((const char*)cell + 64 + s * 8);
    return r;
}

// store fe half2 pair for global rank pair (gr, gr+1) of point row prow into A tile
__device__ __forceinline__ void st_fe(char* smA, int prow, int gr, float flo, float fhi)
{
    *(__half2*)(smA + (prow * ASTR + gr) * 2) = __floats2half2_rn(flo, fhi);
}

// one segment: fp16 bilinear corners * fp32 vec lerp -> fp16 fe into A tile
__device__ __forceinline__ void fe_seg(
    const PC& c00, const PC& c01, const PC& c10, const PC& c11,
    const float* __restrict__ v0, const float* __restrict__ v1, int s,
    float fh, float fw, float fv, int seg, int prow, char* smA)
{
    float w00 = (1.0f - fh) * (1.0f - fw);
    float w01 = (1.0f - fh) * fw;
    float w10 = fh * (1.0f - fw);
    float w11 = fh * fw;
    u64 W00 = pk2(w00, w00), W01 = pk2(w01, w01);
    u64 W10 = pk2(w10, w10), W11 = pk2(w11, w11);
    u64 FV  = pk2(fv, fv),  GV = pk2(1.0f - fv, 1.0f - fv);

    float4 u0 = *(const float4*)(v0 + 8 * s);
    float4 u1 = *(const float4*)(v0 + 8 * s + 4);
    float4 ub = *(const float4*)(v0 + 32 + 4 * s);
    float4 q0 = *(const float4*)(v1 + 8 * s);
    float4 q1 = *(const float4*)(v1 + 8 * s + 4);
    float4 qb = *(const float4*)(v1 + 32 + 4 * s);

    const unsigned* a00 = (const unsigned*)&c00.a;
    const unsigned* a01 = (const unsigned*)&c01.a;
    const unsigned* a10 = (const unsigned*)&c10.a;
    const unsigned* a11 = (const unsigned*)&c11.a;
    u64 UA[4] = { pk2(u0.x, u0.y), pk2(u0.z, u0.w), pk2(u1.x, u1.y), pk2(u1.z, u1.w) };
    u64 QA[4] = { pk2(q0.x, q0.y), pk2(q0.z, q0.w), pk2(q1.x, q1.y), pk2(q1.z, q1.w) };

    int rbA = seg * 48 + 8 * s;
    #pragma unroll
    for (int k = 0; k < 4; k++) {
        u64 t = f2mul(W00, h2f2(a00[k]));
        t = f2fma(W01, h2f2(a01[k]), t);
        t = f2fma(W10, h2f2(a10[k]), t);
        t = f2fma(W11, h2f2(a11[k]), t);
        u64 v = f2fma(FV, QA[k], f2mul(GV, UA[k]));
        u64 fe = f2mul(t, v);
        float flo, fhi;
        upk2(fe, flo, fhi);
        st_fe(smA, prow, rbA + 2 * k, flo, fhi);
    }

    const unsigned* b00 = (const unsigned*)&c00.b;
    const unsigned* b01 = (const unsigned*)&c01.b;
    const unsigned* b10 = (const unsigned*)&c10.b;
    const unsigned* b11 = (const unsigned*)&c11.b;
    u64 UB[2] = { pk2(ub.x, ub.y), pk2(ub.z, ub.w) };
    u64 QB[2] = { pk2(qb.x, qb.y), pk2(qb.z, qb.w) };

    int rbB = seg * 48 + 32 + 4 * s;
    #pragma unroll
    for (int k = 0; k < 2; k++) {
        u64 t = f2mul(W00, h2f2(b00[k]));
        t = f2fma(W01, h2f2(b01[k]), t);
        t = f2fma(W10, h2f2(b10[k]), t);
        t = f2fma(W11, h2f2(b11[k]), t);
        u64 v = f2fma(FV, QB[k], f2mul(GV, UB[k]));
        u64 fe = f2mul(t, v);
        float flo, fhi;
        upk2(fe, flo, fhi);
        st_fe(smA, prow, rbB + 2 * k, flo, fhi);
    }
}

__global__ void __launch_bounds__(256, 2) sample_kernel(
    const float* __restrict__ xyz, const float* __restrict__ fvec,
    float* __restrict__ out)
{
    extern __shared__ char sm[];
    uint32_t smb = smem_u32(sm);

    int tid  = threadIdx.x;
    int lane = tid & 31;
    int warp = tid >> 5;
    int s    = lane & 3;
    int pw   = lane >> 2;
    int pp   = warp * 8 + pw;       // 0..63 within a pass
    int base = blockIdx.x * 128;

    // B fill: F as fp16 [144 k][40 halves], cols >= 27 zero
    for (int i = tid; i < 144 * BSTR / 2; i += 256) {   // half2 index
        int k  = i / (BSTR / 2);
        int np = i - k * (BSTR / 2);
        int n0 = 2 * np;
        float f0 = (n0     < NC) ? fvec[k * NC + n0]     : 0.0f;
        float f1 = (n0 + 1 < NC) ? fvec[k * NC + n0 + 1] : 0.0f;
        *(__half2*)(sm + OFF_B + (k * BSTR + n0) * 2) = __floats2half2_rn(f0, f1);
    }
    // xyz staging (128 points, clamp tail)
    float* sxyz = (float*)(sm + OFF_XYZ);
    for (int i = tid; i < 384; i += 256) {
        long g = (long)base * 3 + i;
        sxyz[i] = (g < (long)NPTS * 3) ? xyz[g] : 0.5f;
    }
    __syncthreads();
    char* smA = sm + OFF_A;

    #pragma unroll
    for (int pass = 0; pass < 2; pass++) {
        int prow = pass * 64 + pp;
        float x = sxyz[prow * 3 + 0];
        float y = sxyz[prow * 3 + 1];
        float z = sxyz[prow * 3 + 2];

        int ix0, ix1, iy0, iy1, iz0, iz1;
        float fx, fy, fz;
        prep_coord(x * 2.0f - 1.0f, DX, ix0, ix1, fx);
        prep_coord(y * 2.0f - 1.0f, DY, iy0, iy1, fy);
        prep_coord(z * 2.0f - 1.0f, DZ, iz0, iz1, fz);

        // pipelined gathers: seg0 + prefetch seg1, compute seg0, ...
        PC c00 = ldpc(g_xyH + (u64)(ix0 * DY + iy0) * PSTR, s);
        PC c01 = ldpc(g_xyH + (u64)(ix0 * DY + iy1) * PSTR, s);
        PC c10 = ldpc(g_xyH + (u64)(ix1 * DY + iy0) * PSTR, s);
        PC c11 = ldpc(g_xyH + (u64)(ix1 * DY + iy1) * PSTR, s);

        PC n00 = ldpc(g_xzH + (u64)(ix0 * DZ + iz0) * PSTR, s);
        PC n01 = ldpc(g_xzH + (u64)(ix0 * DZ + iz1) * PSTR, s);
        PC n10 = ldpc(g_xzH + (u64)(ix1 * DZ + iz0) * PSTR, s);
        PC n11 = ldpc(g_xzH + (u64)(ix1 * DZ + iz1) * PSTR, s);

        fe_seg(c00, c01, c10, c11, g_zvT + iz0 * RNK, g_zvT + iz1 * RNK, s,
               fx, fy, fz, 0, prow, smA);

        c00 = ldpc(g_yzH + (u64)(iy0 * DZ + iz0) * PSTR, s);
        c01 = ldpc(g_yzH + (u64)(iy0 * DZ + iz1) * PSTR, s);
        c10 = ldpc(g_yzH + (u64)(iy1 * DZ + iz0) * PSTR, s);
        c11 = ldpc(g_yzH + (u64)(iy1 * DZ + iz1) * PSTR, s);

        fe_seg(n00, n01, n10, n11, g_yvT + iy0 * RNK, g_yvT + iy1 * RNK, s,
               fx, fz, fy, 1, prow, smA);

        fe_seg(c00, c01, c10, c11, g_xvT + ix0 * RNK, g_xvT + ix1 * RNK, s,
               fy, fz, fx, 2, prow, smA);
    }

    __syncthreads();

    // ---- warp-level HMMA matvec: D[16w..16w+15][0..31] = A rows @ B ----
    float d[4][4];
    #pragma unroll
    for (int t = 0; t < 4; t++) {
        #pragma unroll
        for (int j = 0; j < 4; j++) d[t][j] = 0.0f;
    }

    // A addr: lane l -> row (16w + (l&15)), k-offset (l>>4)*8
    uint32_t aAddr = smb + OFF_A +
                     (uint32_t)(((warp * 16 + (lane & 15)) * ASTR + (lane >> 4) * 8) * 2);
    // B addr: lane l -> k-row (l&15), n-offset (l>>4)*8
    uint32_t bAddr = smb + OFF_B +
                     (uint32_t)(((lane & 15) * BSTR + (lane >> 4) * 8) * 2);

    #pragma unroll
    for (int k = 0; k < 9; k++) {
        uint32_t a[4], b0[4], b1[4];
        ldsm_x4(aAddr + k * 32, a);                       // 16 halves = 32 B per k-step
        ldsm_x4_t(bAddr + k * 16 * BSTR * 2, b0);         // n 0..15
        ldsm_x4_t(bAddr + k * 16 * BSTR * 2 + 32, b1);    // n 16..31
        mma16816(d[0], a, b0[0], b0[1]);
        mma16816(d[1], a, b0[2], b0[3]);
        mma16816(d[2], a, b1[0], b1[1]);
        mma16816(d[3], a, b1[2], b1[3]);
    }

    __syncthreads();   // all ldmatrix reads of A done; reuse A as stage

    // stage: [128][36] f32
    float* stage = (float*)(sm + OFF_A);
    {
        int r0 = warp * 16 + (lane >> 2);
        int c0 = 2 * (lane & 3);
        #pragma unroll
        for (int t = 0; t < 4; t++) {
            *(float2*)(stage + r0 * 36 + 8 * t + c0)       = make_float2(d[t][0], d[t][1]);
            *(float2*)(stage + (r0 + 8) * 36 + 8 * t + c0) = make_float2(d[t][2], d[t][3]);
        }
    }
    __syncthreads();

    int lim = (NPTS - base) * NC;
    if (lim > 128 * NC) lim = 128 * NC;
    for (int i = tid; i < lim; i += 256) {
        int pt = i / NC;
        int c  = i - pt * NC;
        out[(long)base * NC + i] = stage[pt * 36 + c];
    }
}

extern "C" void kernel_launch(void* const* d_in, const int* in_sizes, int n_in,
                              void* d_out, int out_size)
{
    const float* xyz = (const float*)d_in[0];
    const float* xyp = (const float*)d_in[1];
    const float* xzp = (const float*)d_in[2];
    const float* yzp = (const float*)d_in[3];
    const float* xv  = (const float*)d_in[4];
    const float* yv  = (const float*)d_in[5];
    const float* zv  = (const float*)d_in[6];
    const float* fv  = (const float*)d_in[7];
    float* out = (float*)d_out;

    cudaFuncSetAttribute(sample_kernel,
                         cudaFuncAttributeMaxDynamicSharedMemorySize, SMEM_TOT);

    transpose_all<<<2121, 128>>>(xyp, xzp, yzp, xv, yv, zv);
    sample_kernel<<<(NPTS + 127) / 128, 256, SMEM_TOT>>>(xyz, fv, out);
}

// round 12
// speedup vs baseline: 2.6063x; 1.1140x over previous
#include <cuda_runtime.h>
#include <cuda_fp16.h>
#include <cstdint>

#define NPTS 1000000
#define DX 300
#define DY 300
#define DZ 300
#define RNK  48
#define PSTR 64    // padded halves per plane cell (128 B, line-aligned)
#define NC   27

// fp16 planes (cell-major, 64-half padded rows), fp16 vectors (cell-major, 48 halves)
__device__ __align__(16) __half g_xyH[DX * DY * PSTR];
__device__ __align__(16) __half g_xzH[DX * DZ * PSTR];
__device__ __align__(16) __half g_yzH[DY * DZ * PSTR];
__device__ __align__(16) __half g_xvH[DX * RNK];
__device__ __align__(16) __half g_yvH[DY * RNK];
__device__ __align__(16) __half g_zvH[DZ * RNK];

typedef unsigned long long u64;

// ---------- smem layout (dynamic, bytes) ----------
// A: fe tile [128 pts][152 halves]  (stride 304 B, ldmatrix conflict-free)
// B: F tile  [144 k  ][40 halves]   (stride 80 B, ldmatrix conflict-free; cols 27..31 = 0)
// stage (reuses A): [128 pts][36 f32]
#define ASTR 152
#define BSTR 40
#define OFF_A    0
#define OFF_B    (128 * ASTR * 2)                 // 38912
#define OFF_XYZ  (OFF_B + 144 * BSTR * 2)         // 50432
#define SMEM_TOT (OFF_XYZ + 128 * 3 * 4)          // 51968

// ---------- packed f32x2 helpers ----------
__device__ __forceinline__ u64 pk2(float lo, float hi) {
    u64 r;
    asm("mov.b64 %0, {%1, %2};" : "=l"(r) : "f"(lo), "f"(hi));
    return r;
}
__device__ __forceinline__ void upk2(u64 v, float& lo, float& hi) {
    asm("mov.b64 {%0, %1}, %2;" : "=f"(lo), "=f"(hi) : "l"(v));
}
__device__ __forceinline__ u64 f2mul(u64 a, u64 b) {
    u64 d;
    asm("mul.rn.f32x2 %0, %1, %2;" : "=l"(d) : "l"(a), "l"(b));
    return d;
}
__device__ __forceinline__ u64 f2fma(u64 a, u64 b, u64 c) {
    u64 d;
    asm("fma.rn.f32x2 %0, %1, %2, %3;" : "=l"(d) : "l"(a), "l"(b), "l"(c));
    return d;
}
__device__ __forceinline__ u64 h2f2(unsigned int h) {
    float2 f = __half22float2(*(__half2*)&h);
    return pk2(f.x, f.y);
}
__device__ __forceinline__ uint32_t smem_u32(const void* p) {
    uint32_t a;
    asm("{ .reg .u64 t; cvta.to.shared.u64 t, %1; cvt.u32.u64 %0, t; }" : "=r"(a) : "l"(p));
    return a;
}

// ---------- ldmatrix / mma.sync ----------
__device__ __forceinline__ void ldsm_x4(uint32_t addr, uint32_t r[4]) {
    asm volatile("ldmatrix.sync.aligned.m8n8.x4.shared.b16 {%0,%1,%2,%3}, [%4];"
                 : "=r"(r[0]), "=r"(r[1]), "=r"(r[2]), "=r"(r[3]) : "r"(addr));
}
__device__ __forceinline__ void ldsm_x4_t(uint32_t addr, uint32_t r[4]) {
    asm volatile("ldmatrix.sync.aligned.m8n8.x4.trans.shared.b16 {%0,%1,%2,%3}, [%4];"
                 : "=r"(r[0]), "=r"(r[1]), "=r"(r[2]), "=r"(r[3]) : "r"(addr));
}
__device__ __forceinline__ void mma16816(float d[4], const uint32_t a[4],
                                         uint32_t b0, uint32_t b1) {
    asm volatile(
        "mma.sync.aligned.m16n8k16.row.col.f32.f16.f16.f32 "
        "{%0,%1,%2,%3}, {%4,%5,%6,%7}, {%8,%9}, {%0,%1,%2,%3};"
        : "+f"(d[0]), "+f"(d[1]), "+f"(d[2]), "+f"(d[3])
        : "r"(a[0]), "r"(a[1]), "r"(a[2]), "r"(a[3]), "r"(b0), "r"(b1));
}

// ---------- merged transpose/convert ----------
__global__ void __launch_bounds__(128) transpose_all(
    const float* __restrict__ xy, const float* __restrict__ xz,
    const float* __restrict__ yz, const float* __restrict__ xv,
    const float* __restrict__ yv, const float* __restrict__ zv)
{
    __shared__ float tile[RNK][129];
    int b = blockIdx.x;
    int t = threadIdx.x;

    if (b < 2112) {
        const float* src;
        __half* dst;
        int base;
        const int cells = DX * DY;
        if (b < 704)       { src = xy; dst = g_xyH; base = b * 128; }
        else if (b < 1408) { src = xz; dst = g_xzH; base = (b - 704) * 128; }
        else               { src = yz; dst = g_yzH; base = (b - 1408) * 128; }

        int nc = cells - base;
        if (nc > 128) nc = 128;

        #pragma unroll
        for (int r = 0; r < RNK; r++) {
            if (t < nc) tile[r][t] = src[r * cells + base + t];
        }
        __syncthreads();
        __half2* dst2 = (__half2*)dst;
        for (int i = t; i < nc * 32; i += 128) {
            int cl = i >> 5;
            int p  = i & 31;
            float lo = (2 * p     < RNK) ? tile[2 * p][cl]     : 0.0f;
            float hi = (2 * p + 1 < RNK) ? tile[2 * p + 1][cl] : 0.0f;
            dst2[(u64)(base + cl) * 32 + p] = __floats2half2_rn(lo, hi);
        }
    } else {
        int vb = b - 2112;
        int vi = vb / 3;
        int base = (vb % 3) * 128;
        const int cells = DX;
        const float* src = (vi == 0) ? xv : ((vi == 1) ? yv : zv);
        __half* dst = (vi == 0) ? g_xvH : ((vi == 1) ? g_yvH : g_zvH);

        int nc = cells - base;
        if (nc > 128) nc = 128;
        if (nc <= 0) return;

        #pragma unroll
        for (int r = 0; r < RNK; r++) {
            if (t < nc) tile[r][t] = src[r * cells + base + t];
        }
        __syncthreads();
        __half2* dst2 = (__half2*)dst;
        for (int i = t; i < nc * 24; i += 128) {    // 24 half2 per cell
            int cl = i / 24;
            int p  = i - cl * 24;
            dst2[(base + cl) * 24 + p] =
                __floats2half2_rn(tile[2 * p][cl], tile[2 * p + 1][cl]);
        }
    }
}

__device__ __forceinline__ void prep_coord(float g, int L, int& i0, int& i1, float& f)
{
    float t  = (g + 1.0f) * 0.5f;
    float ih = t * (float)(L - 1);
    int i = (int)floorf(ih);
    i = max(0, min(i, L - 1));
    i0 = i;
    i1 = min(i + 1, L - 1);
    f = ih - (float)i;
}

// one fp16 cell gather for lane s: 16B (ranks 8s..8s+7) + 8B (ranks 32+4s..+3).
// Works for plane cells (128 B stride) and vector cells (96 B stride).
struct PC { uint4 a; uint2 b; };
__device__ __forceinline__ PC ldpc(const __half* cell, int s)
{
    PC r;
    r.a = *(const uint4*)((const char*)cell + s * 16);
    r.b = *(const uint2*)((const char*)cell + 64 + s * 8);
    return r;
}

// store fe half2 pair for global rank pair (gr, gr+1) of point row prow into A tile
__device__ __forceinline__ void st_fe(char* smA, int prow, int gr, float flo, float fhi)
{
    *(__half2*)(smA + (prow * ASTR + gr) * 2) = __floats2half2_rn(flo, fhi);
}

// one segment: fp16 bilinear corners * fp16 vec lerp -> fp16 fe into A tile
__device__ __forceinline__ void fe_seg(
    const PC& c00, const PC& c01, const PC& c10, const PC& c11,
    const PC& vu, const PC& vw, int s,
    float fh, float fw, float fv, int seg, int prow, char* smA)
{
    float w00 = (1.0f - fh) * (1.0f - fw);
    float w01 = (1.0f - fh) * fw;
    float w10 = fh * (1.0f - fw);
    float w11 = fh * fw;
    u64 W00 = pk2(w00, w00), W01 = pk2(w01, w01);
    u64 W10 = pk2(w10, w10), W11 = pk2(w11, w11);
    u64 FV  = pk2(fv, fv),  GV = pk2(1.0f - fv, 1.0f - fv);

    const unsigned* a00 = (const unsigned*)&c00.a;
    const unsigned* a01 = (const unsigned*)&c01.a;
    const unsigned* a10 = (const unsigned*)&c10.a;
    const unsigned* a11 = (const unsigned*)&c11.a;
    const unsigned* ua  = (const unsigned*)&vu.a;
    const unsigned* wa  = (const unsigned*)&vw.a;

    int rbA = seg * 48 + 8 * s;
    #pragma unroll
    for (int k = 0; k < 4; k++) {
        u64 t = f2mul(W00, h2f2(a00[k]));
        t = f2fma(W01, h2f2(a01[k]), t);
        t = f2fma(W10, h2f2(a10[k]), t);
        t = f2fma(W11, h2f2(a11[k]), t);
        u64 v = f2fma(FV, h2f2(wa[k]), f2mul(GV, h2f2(ua[k])));
        u64 fe = f2mul(t, v);
        float flo, fhi;
        upk2(fe, flo, fhi);
        st_fe(smA, prow, rbA + 2 * k, flo, fhi);
    }

    const unsigned* b00 = (const unsigned*)&c00.b;
    const unsigned* b01 = (const unsigned*)&c01.b;
    const unsigned* b10 = (const unsigned*)&c10.b;
    const unsigned* b11 = (const unsigned*)&c11.b;
    const unsigned* ub  = (const unsigned*)&vu.b;
    const unsigned* wb  = (const unsigned*)&vw.b;

    int rbB = seg * 48 + 32 + 4 * s;
    #pragma unroll
    for (int k = 0; k < 2; k++) {
        u64 t = f2mul(W00, h2f2(b00[k]));
        t = f2fma(W01, h2f2(b01[k]), t);
        t = f2fma(W10, h2f2(b10[k]), t);
        t = f2fma(W11, h2f2(b11[k]), t);
        u64 v = f2fma(FV, h2f2(wb[k]), f2mul(GV, h2f2(ub[k])));
        u64 fe = f2mul(t, v);
        float flo, fhi;
        upk2(fe, flo, fhi);
        st_fe(smA, prow, rbB + 2 * k, flo, fhi);
    }
}

__global__ void __launch_bounds__(256, 2) sample_kernel(
    const float* __restrict__ xyz, const float* __restrict__ fvec,
    float* __restrict__ out)
{
    extern __shared__ char sm[];
    uint32_t smb = smem_u32(sm);

    int tid  = threadIdx.x;
    int lane = tid & 31;
    int warp = tid >> 5;
    int s    = lane & 3;
    int pw   = lane >> 2;
    int pp   = warp * 8 + pw;       // 0..63 within a pass
    int base = blockIdx.x * 128;

    // B fill: F as fp16 [144 k][40 halves], cols >= 27 zero
    for (int i = tid; i < 144 * BSTR / 2; i += 256) {   // half2 index
        int k  = i / (BSTR / 2);
        int np = i - k * (BSTR / 2);
        int n0 = 2 * np;
        float f0 = (n0     < NC) ? fvec[k * NC + n0]     : 0.0f;
        float f1 = (n0 + 1 < NC) ? fvec[k * NC + n0 + 1] : 0.0f;
        *(__half2*)(sm + OFF_B + (k * BSTR + n0) * 2) = __floats2half2_rn(f0, f1);
    }
    // xyz staging (128 points, clamp tail)
    float* sxyz = (float*)(sm + OFF_XYZ);
    for (int i = tid; i < 384; i += 256) {
        long g = (long)base * 3 + i;
        sxyz[i] = (g < (long)NPTS * 3) ? xyz[g] : 0.5f;
    }
    __syncthreads();
    char* smA = sm + OFF_A;

    #pragma unroll
    for (int pass = 0; pass < 2; pass++) {
        int prow = pass * 64 + pp;
        float x = sxyz[prow * 3 + 0];
        float y = sxyz[prow * 3 + 1];
        float z = sxyz[prow * 3 + 2];

        int ix0, ix1, iy0, iy1, iz0, iz1;
        float fx, fy, fz;
        prep_coord(x * 2.0f - 1.0f, DX, ix0, ix1, fx);
        prep_coord(y * 2.0f - 1.0f, DY, iy0, iy1, fy);
        prep_coord(z * 2.0f - 1.0f, DZ, iz0, iz1, fz);

        // pipelined gathers: seg0 + seg1 corners/vecs up front, then compute
        PC c00 = ldpc(g_xyH + (u64)(ix0 * DY + iy0) * PSTR, s);
        PC c01 = ldpc(g_xyH + (u64)(ix0 * DY + iy1) * PSTR, s);
        PC c10 = ldpc(g_xyH + (u64)(ix1 * DY + iy0) * PSTR, s);
        PC c11 = ldpc(g_xyH + (u64)(ix1 * DY + iy1) * PSTR, s);
        PC vz0 = ldpc(g_zvH + iz0 * RNK, s);
        PC vz1 = ldpc(g_zvH + iz1 * RNK, s);

        PC n00 = ldpc(g_xzH + (u64)(ix0 * DZ + iz0) * PSTR, s);
        PC n01 = ldpc(g_xzH + (u64)(ix0 * DZ + iz1) * PSTR, s);
        PC n10 = ldpc(g_xzH + (u64)(ix1 * DZ + iz0) * PSTR, s);
        PC n11 = ldpc(g_xzH + (u64)(ix1 * DZ + iz1) * PSTR, s);
        PC vy0 = ldpc(g_yvH + iy0 * RNK, s);
        PC vy1 = ldpc(g_yvH + iy1 * RNK, s);

        fe_seg(c00, c01, c10, c11, vz0, vz1, s, fx, fy, fz, 0, prow, smA);

        c00 = ldpc(g_yzH + (u64)(iy0 * DZ + iz0) * PSTR, s);
        c01 = ldpc(g_yzH + (u64)(iy0 * DZ + iz1) * PSTR, s);
        c10 = ldpc(g_yzH + (u64)(iy1 * DZ + iz0) * PSTR, s);
        c11 = ldpc(g_yzH + (u64)(iy1 * DZ + iz1) * PSTR, s);
        PC vx0 = ldpc(g_xvH + ix0 * RNK, s);
        PC vx1 = ldpc(g_xvH + ix1 * RNK, s);

        fe_seg(n00, n01, n10, n11, vy0, vy1, s, fx, fz, fy, 1, prow, smA);

        fe_seg(c00, c01, c10, c11, vx0, vx1, s, fy, fz, fx, 2, prow, smA);
    }

    __syncthreads();

    // ---- warp-level HMMA matvec: D[16w..16w+15][0..31] = A rows @ B ----
    float d[4][4];
    #pragma unroll
    for (int t = 0; t < 4; t++) {
        #pragma unroll
        for (int j = 0; j < 4; j++) d[t][j] = 0.0f;
    }

    // A addr: lane l -> row (16w + (l&15)), k-offset (l>>4)*8
    uint32_t aAddr = smb + OFF_A +
                     (uint32_t)(((warp * 16 + (lane & 15)) * ASTR + (lane >> 4) * 8) * 2);
    // B addr: lane l -> k-row (l&15), n-offset (l>>4)*8
    uint32_t bAddr = smb + OFF_B +
                     (uint32_t)(((lane & 15) * BSTR + (lane >> 4) * 8) * 2);

    #pragma unroll
    for (int k = 0; k < 9; k++) {
        uint32_t a[4], b0[4], b1[4];
        ldsm_x4(aAddr + k * 32, a);                       // 16 halves = 32 B per k-step
        ldsm_x4_t(bAddr + k * 16 * BSTR * 2, b0);         // n 0..15
        ldsm_x4_t(bAddr + k * 16 * BSTR * 2 + 32, b1);    // n 16..31
        mma16816(d[0], a, b0[0], b0[1]);
        mma16816(d[1], a, b0[2], b0[3]);
        mma16816(d[2], a, b1[0], b1[1]);
        mma16816(d[3], a, b1[2], b1[3]);
    }

    __syncthreads();   // all ldmatrix reads of A done; reuse A as stage

    // stage: [128][36] f32
    float* stage = (float*)(sm + OFF_A);
    {
        int r0 = warp * 16 + (lane >> 2);
        int c0 = 2 * (lane & 3);
        #pragma unroll
        for (int t = 0; t < 4; t++) {
            *(float2*)(stage + r0 * 36 + 8 * t + c0)       = make_float2(d[t][0], d[t][1]);
            *(float2*)(stage + (r0 + 8) * 36 + 8 * t + c0) = make_float2(d[t][2], d[t][3]);
        }
    }
    __syncthreads();

    int lim = (NPTS - base) * NC;
    if (lim > 128 * NC) lim = 128 * NC;
    for (int i = tid; i < lim; i += 256) {
        int pt = i / NC;
        int c  = i - pt * NC;
        out[(long)base * NC + i] = stage[pt * 36 + c];
    }
}

extern "C" void kernel_launch(void* const* d_in, const int* in_sizes, int n_in,
                              void* d_out, int out_size)
{
    const float* xyz = (const float*)d_in[0];
    const float* xyp = (const float*)d_in[1];
    const float* xzp = (const float*)d_in[2];
    const float* yzp = (const float*)d_in[3];
    const float* xv  = (const float*)d_in[4];
    const float* yv  = (const float*)d_in[5];
    const float* zv  = (const float*)d_in[6];
    const float* fv  = (const float*)d_in[7];
    float* out = (float*)d_out;

    cudaFuncSetAttribute(sample_kernel,
                         cudaFuncAttributeMaxDynamicSharedMemorySize, SMEM_TOT);

    transpose_all<<<2121, 128>>>(xyp, xzp, yzp, xv, yv, zv);
    sample_kernel<<<(NPTS + 127) / 128, 256, SMEM_TOT>>>(xyz, fv, out);
}

// round 13
// speedup vs baseline: 2.9285x; 1.1236x over previous
#include <cuda_runtime.h>
#include <cuda_fp16.h>
#include <cstdint>

#define NPTS 1000000
#define DX 300
#define DY 300
#define DZ 300
#define RNK  48
#define PSTR 64    // padded halves per plane cell (128 B, line-aligned)
#define NC   27

// fp16 planes (cell-major, 64-half padded rows), fp16 vectors (cell-major, 48 halves)
__device__ __align__(16) __half g_xyH[DX * DY * PSTR];
__device__ __align__(16) __half g_xzH[DX * DZ * PSTR];
__device__ __align__(16) __half g_yzH[DY * DZ * PSTR];
__device__ __align__(16) __half g_xvH[DX * RNK];
__device__ __align__(16) __half g_yvH[DY * RNK];
__device__ __align__(16) __half g_zvH[DZ * RNK];

typedef unsigned long long u64;

// ---------- smem layout (dynamic, bytes) ----------
// A: fe tile [128 pts][152 halves]  (stride 304 B, ldmatrix conflict-free)
// B: F tile  [144 k  ][40 halves]   (stride 80 B, ldmatrix conflict-free; cols 27..31 = 0)
// stage (reuses A): [128 pts][36 f32]
#define ASTR 152
#define BSTR 40
#define OFF_A    0
#define OFF_B    (128 * ASTR * 2)                 // 38912
#define OFF_XYZ  (OFF_B + 144 * BSTR * 2)         // 50432
#define SMEM_TOT (OFF_XYZ + 128 * 3 * 4)          // 51968

// ---------- packed f32x2 helpers ----------
__device__ __forceinline__ u64 pk2(float lo, float hi) {
    u64 r;
    asm("mov.b64 %0, {%1, %2};" : "=l"(r) : "f"(lo), "f"(hi));
    return r;
}
__device__ __forceinline__ void upk2(u64 v, float& lo, float& hi) {
    asm("mov.b64 {%0, %1}, %2;" : "=f"(lo), "=f"(hi) : "l"(v));
}
__device__ __forceinline__ u64 f2mul(u64 a, u64 b) {
    u64 d;
    asm("mul.rn.f32x2 %0, %1, %2;" : "=l"(d) : "l"(a), "l"(b));
    return d;
}
__device__ __forceinline__ u64 f2fma(u64 a, u64 b, u64 c) {
    u64 d;
    asm("fma.rn.f32x2 %0, %1, %2, %3;" : "=l"(d) : "l"(a), "l"(b), "l"(c));
    return d;
}
__device__ __forceinline__ u64 h2f2(unsigned int h) {
    float2 f = __half22float2(*(__half2*)&h);
    return pk2(f.x, f.y);
}
__device__ __forceinline__ uint32_t smem_u32(const void* p) {
    uint32_t a;
    asm("{ .reg .u64 t; cvta.to.shared.u64 t, %1; cvt.u32.u64 %0, t; }" : "=r"(a) : "l"(p));
    return a;
}

// ---------- ldmatrix / mma.sync ----------
__device__ __forceinline__ void ldsm_x4(uint32_t addr, uint32_t r[4]) {
    asm volatile("ldmatrix.sync.aligned.m8n8.x4.shared.b16 {%0,%1,%2,%3}, [%4];"
                 : "=r"(r[0]), "=r"(r[1]), "=r"(r[2]), "=r"(r[3]) : "r"(addr));
}
__device__ __forceinline__ void ldsm_x4_t(uint32_t addr, uint32_t r[4]) {
    asm volatile("ldmatrix.sync.aligned.m8n8.x4.trans.shared.b16 {%0,%1,%2,%3}, [%4];"
                 : "=r"(r[0]), "=r"(r[1]), "=r"(r[2]), "=r"(r[3]) : "r"(addr));
}
__device__ __forceinline__ void mma16816(float d[4], const uint32_t a[4],
                                         uint32_t b0, uint32_t b1) {
    asm volatile(
        "mma.sync.aligned.m16n8k16.row.col.f32.f16.f16.f32 "
        "{%0,%1,%2,%3}, {%4,%5,%6,%7}, {%8,%9}, {%0,%1,%2,%3};"
        : "+f"(d[0]), "+f"(d[1]), "+f"(d[2]), "+f"(d[3])
        : "r"(a[0]), "r"(a[1]), "r"(a[2]), "r"(a[3]), "r"(b0), "r"(b1));
}

// ---------- merged transpose/convert ----------
__global__ void __launch_bounds__(128) transpose_all(
    const float* __restrict__ xy, const float* __restrict__ xz,
    const float* __restrict__ yz, const float* __restrict__ xv,
    const float* __restrict__ yv, const float* __restrict__ zv)
{
    __shared__ float tile[RNK][129];
    int b = blockIdx.x;
    int t = threadIdx.x;

    if (b < 2112) {
        const float* src;
        __half* dst;
        int base;
        const int cells = DX * DY;
        if (b < 704)       { src = xy; dst = g_xyH; base = b * 128; }
        else if (b < 1408) { src = xz; dst = g_xzH; base = (b - 704) * 128; }
        else               { src = yz; dst = g_yzH; base = (b - 1408) * 128; }

        int nc = cells - base;
        if (nc > 128) nc = 128;

        #pragma unroll
        for (int r = 0; r < RNK; r++) {
            if (t < nc) tile[r][t] = src[r * cells + base + t];
        }
        __syncthreads();
        __half2* dst2 = (__half2*)dst;
        for (int i = t; i < nc * 32; i += 128) {
            int cl = i >> 5;
            int p  = i & 31;
            float lo = (2 * p     < RNK) ? tile[2 * p][cl]     : 0.0f;
            float hi = (2 * p + 1 < RNK) ? tile[2 * p + 1][cl] : 0.0f;
            dst2[(u64)(base + cl) * 32 + p] = __floats2half2_rn(lo, hi);
        }
    } else {
        int vb = b - 2112;
        int vi = vb / 3;
        int base = (vb % 3) * 128;
        const int cells = DX;
        const float* src = (vi == 0) ? xv : ((vi == 1) ? yv : zv);
        __half* dst = (vi == 0) ? g_xvH : ((vi == 1) ? g_yvH : g_zvH);

        int nc = cells - base;
        if (nc > 128) nc = 128;
        if (nc <= 0) return;

        #pragma unroll
        for (int r = 0; r < RNK; r++) {
            if (t < nc) tile[r][t] = src[r * cells + base + t];
        }
        __syncthreads();
        __half2* dst2 = (__half2*)dst;
        for (int i = t; i < nc * 24; i += 128) {    // 24 half2 per cell
            int cl = i / 24;
            int p  = i - cl * 24;
            dst2[(base + cl) * 24 + p] =
                __floats2half2_rn(tile[2 * p][cl], tile[2 * p + 1][cl]);
        }
    }
}

__device__ __forceinline__ void prep_coord(float g, int L, int& i0, int& i1, float& f)
{
    float t  = (g + 1.0f) * 0.5f;
    float ih = t * (float)(L - 1);
    int i = (int)floorf(ih);
    i = max(0, min(i, L - 1));
    i0 = i;
    i1 = min(i + 1, L - 1);
    f = ih - (float)i;
}

// one fp16 cell gather for lane s: 16B (ranks 8s..8s+7) + 8B (ranks 32+4s..+3).
// Works for plane cells (128 B stride) and vector cells (96 B stride).
struct PC { uint4 a; uint2 b; };
__device__ __forceinline__ PC ldpc(const __half* cell, int s)
{
    PC r;
    r.a = *(const uint4*)((const char*)cell + s * 16);
    r.b = *(const uint2*)((const char*)cell + 64 + s * 8);
    return r;
}

// store fe half2 pair for global rank pair (gr, gr+1) of point row prow into A tile
__device__ __forceinline__ void st_fe(char* smA, int prow, int gr, float flo, float fhi)
{
    *(__half2*)(smA + (prow * ASTR + gr) * 2) = __floats2half2_rn(flo, fhi);
}

// one segment: fp16 bilinear corners * fp16 vec lerp -> fp16 fe into A tile
__device__ __forceinline__ void fe_seg(
    const PC& c00, const PC& c01, const PC& c10, const PC& c11,
    const PC& vu, const PC& vw, int s,
    float fh, float fw, float fv, int seg, int prow, char* smA)
{
    float w00 = (1.0f - fh) * (1.0f - fw);
    float w01 = (1.0f - fh) * fw;
    float w10 = fh * (1.0f - fw);
    float w11 = fh * fw;
    u64 W00 = pk2(w00, w00), W01 = pk2(w01, w01);
    u64 W10 = pk2(w10, w10), W11 = pk2(w11, w11);
    u64 FV  = pk2(fv, fv),  GV = pk2(1.0f - fv, 1.0f - fv);

    const unsigned* a00 = (const unsigned*)&c00.a;
    const unsigned* a01 = (const unsigned*)&c01.a;
    const unsigned* a10 = (const unsigned*)&c10.a;
    const unsigned* a11 = (const unsigned*)&c11.a;
    const unsigned* ua  = (const unsigned*)&vu.a;
    const unsigned* wa  = (const unsigned*)&vw.a;

    int rbA = seg * 48 + 8 * s;
    #pragma unroll
    for (int k = 0; k < 4; k++) {
        u64 t = f2mul(W00, h2f2(a00[k]));
        t = f2fma(W01, h2f2(a01[k]), t);
        t = f2fma(W10, h2f2(a10[k]), t);
        t = f2fma(W11, h2f2(a11[k]), t);
        u64 v = f2fma(FV, h2f2(wa[k]), f2mul(GV, h2f2(ua[k])));
        u64 fe = f2mul(t, v);
        float flo, fhi;
        upk2(fe, flo, fhi);
        st_fe(smA, prow, rbA + 2 * k, flo, fhi);
    }

    const unsigned* b00 = (const unsigned*)&c00.b;
    const unsigned* b01 = (const unsigned*)&c01.b;
    const unsigned* b10 = (const unsigned*)&c10.b;
    const unsigned* b11 = (const unsigned*)&c11.b;
    const unsigned* ub  = (const unsigned*)&vu.b;
    const unsigned* wb  = (const unsigned*)&vw.b;

    int rbB = seg * 48 + 32 + 4 * s;
    #pragma unroll
    for (int k = 0; k < 2; k++) {
        u64 t = f2mul(W00, h2f2(b00[k]));
        t = f2fma(W01, h2f2(b01[k]), t);
        t = f2fma(W10, h2f2(b10[k]), t);
        t = f2fma(W11, h2f2(b11[k]), t);
        u64 v = f2fma(FV, h2f2(wb[k]), f2mul(GV, h2f2(ub[k])));
        u64 fe = f2mul(t, v);
        float flo, fhi;
        upk2(fe, flo, fhi);
        st_fe(smA, prow, rbB + 2 * k, flo, fhi);
    }
}

__global__ void __launch_bounds__(256, 3) sample_kernel(
    const float* __restrict__ xyz, const float* __restrict__ fvec,
    float* __restrict__ out)
{
    extern __shared__ char sm[];
    uint32_t smb = smem_u32(sm);

    int tid  = threadIdx.x;
    int lane = tid & 31;
    int warp = tid >> 5;
    int s    = lane & 3;
    int pw   = lane >> 2;
    int pp   = warp * 8 + pw;       // 0..63 within a pass
    int base = blockIdx.x * 128;

    // B fill: F as fp16 [144 k][40 halves], cols >= 27 zero
    for (int i = tid; i < 144 * BSTR / 2; i += 256) {   // half2 index
        int k  = i / (BSTR / 2);
        int np = i - k * (BSTR / 2);
        int n0 = 2 * np;
        float f0 = (n0     < NC) ? fvec[k * NC + n0]     : 0.0f;
        float f1 = (n0 + 1 < NC) ? fvec[k * NC + n0 + 1] : 0.0f;
        *(__half2*)(sm + OFF_B + (k * BSTR + n0) * 2) = __floats2half2_rn(f0, f1);
    }
    // xyz staging (128 points, clamp tail)
    float* sxyz = (float*)(sm + OFF_XYZ);
    for (int i = tid; i < 384; i += 256) {
        long g = (long)base * 3 + i;
        sxyz[i] = (g < (long)NPTS * 3) ? xyz[g] : 0.5f;
    }
    __syncthreads();
    char* smA = sm + OFF_A;

    for (int pass = 0; pass < 2; pass++) {
        int prow = pass * 64 + pp;
        float x = sxyz[prow * 3 + 0];
        float y = sxyz[prow * 3 + 1];
        float z = sxyz[prow * 3 + 2];

        int ix0, ix1, iy0, iy1, iz0, iz1;
        float fx, fy, fz;
        prep_coord(x * 2.0f - 1.0f, DX, ix0, ix1, fx);
        prep_coord(y * 2.0f - 1.0f, DY, iy0, iy1, fy);
        prep_coord(z * 2.0f - 1.0f, DZ, iz0, iz1, fz);

        // reduced-liveness pipeline: corners of seg0 + seg1 up front (8 PC),
        // vectors just-in-time (L1-hot small tables)
        PC c00 = ldpc(g_xyH + (u64)(ix0 * DY + iy0) * PSTR, s);
        PC c01 = ldpc(g_xyH + (u64)(ix0 * DY + iy1) * PSTR, s);
        PC c10 = ldpc(g_xyH + (u64)(ix1 * DY + iy0) * PSTR, s);
        PC c11 = ldpc(g_xyH + (u64)(ix1 * DY + iy1) * PSTR, s);

        PC n00 = ldpc(g_xzH + (u64)(ix0 * DZ + iz0) * PSTR, s);
        PC n01 = ldpc(g_xzH + (u64)(ix0 * DZ + iz1) * PSTR, s);
        PC n10 = ldpc(g_xzH + (u64)(ix1 * DZ + iz0) * PSTR, s);
        PC n11 = ldpc(g_xzH + (u64)(ix1 * DZ + iz1) * PSTR, s);

        {
            PC vz0 = ldpc(g_zvH + iz0 * RNK, s);
            PC vz1 = ldpc(g_zvH + iz1 * RNK, s);
            fe_seg(c00, c01, c10, c11, vz0, vz1, s, fx, fy, fz, 0, prow, smA);
        }

        // seg2 corners reuse c-slots
        c00 = ldpc(g_yzH + (u64)(iy0 * DZ + iz0) * PSTR, s);
        c01 = ldpc(g_yzH + (u64)(iy0 * DZ + iz1) * PSTR, s);
        c10 = ldpc(g_yzH + (u64)(iy1 * DZ + iz0) * PSTR, s);
        c11 = ldpc(g_yzH + (u64)(iy1 * DZ + iz1) * PSTR, s);

        {
            PC vy0 = ldpc(g_yvH + iy0 * RNK, s);
            PC vy1 = ldpc(g_yvH + iy1 * RNK, s);
            fe_seg(n00, n01, n10, n11, vy0, vy1, s, fx, fz, fy, 1, prow, smA);
        }
        {
            PC vx0 = ldpc(g_xvH + ix0 * RNK, s);
            PC vx1 = ldpc(g_xvH + ix1 * RNK, s);
            fe_seg(c00, c01, c10, c11, vx0, vx1, s, fy, fz, fx, 2, prow, smA);
        }
    }

    __syncthreads();

    // ---- warp-level HMMA matvec: D[16w..16w+15][0..31] = A rows @ B ----
    // accumulators declared here so they don't inflate gather-phase liveness
    float d[4][4];
    #pragma unroll
    for (int t = 0; t < 4; t++) {
        #pragma unroll
        for (int j = 0; j < 4; j++) d[t][j] = 0.0f;
    }

    // A addr: lane l -> row (16w + (l&15)), k-offset (l>>4)*8
    uint32_t aAddr = smb + OFF_A +
                     (uint32_t)(((warp * 16 + (lane & 15)) * ASTR + (lane >> 4) * 8) * 2);
    // B addr: lane l -> k-row (l&15), n-offset (l>>4)*8
    uint32_t bAddr = smb + OFF_B +
                     (uint32_t)(((lane & 15) * BSTR + (lane >> 4) * 8) * 2);

    #pragma unroll
    for (int k = 0; k < 9; k++) {
        uint32_t a[4], b0[4], b1[4];
        ldsm_x4(aAddr + k * 32, a);                       // 16 halves = 32 B per k-step
        ldsm_x4_t(bAddr + k * 16 * BSTR * 2, b0);         // n 0..15
        ldsm_x4_t(bAddr + k * 16 * BSTR * 2 + 32, b1);    // n 16..31
        mma16816(d[0], a, b0[0], b0[1]);
        mma16816(d[1], a, b0[2], b0[3]);
        mma16816(d[2], a, b1[0], b1[1]);
        mma16816(d[3], a, b1[2], b1[3]);
    }

    __syncthreads();   // all ldmatrix reads of A done; reuse A as stage

    // stage: [128][36] f32
    float* stage = (float*)(sm + OFF_A);
    {
        int r0 = warp * 16 + (lane >> 2);
        int c0 = 2 * (lane & 3);
        #pragma unroll
        for (int t = 0; t < 4; t++) {
            *(float2*)(stage + r0 * 36 + 8 * t + c0)       = make_float2(d[t][0], d[t][1]);
            *(float2*)(stage + (r0 + 8) * 36 + 8 * t + c0) = make_float2(d[t][2], d[t][3]);
        }
    }
    __syncthreads();

    int lim = (NPTS - base) * NC;
    if (lim > 128 * NC) lim = 128 * NC;
    for (int i = tid; i < lim; i += 256) {
        int pt = i / NC;
        int c  = i - pt * NC;
        out[(long)base * NC + i] = stage[pt * 36 + c];
    }
}

extern "C" void kernel_launch(void* const* d_in, const int* in_sizes, int n_in,
                              void* d_out, int out_size)
{
    const float* xyz = (const float*)d_in[0];
    const float* xyp = (const float*)d_in[1];
    const float* xzp = (const float*)d_in[2];
    const float* yzp = (const float*)d_in[3];
    const float* xv  = (const float*)d_in[4];
    const float* yv  = (const float*)d_in[5];
    const float* zv  = (const float*)d_in[6];
    const float* fv  = (const float*)d_in[7];
    float* out = (float*)d_out;

    cudaFuncSetAttribute(sample_kernel,
                         cudaFuncAttributeMaxDynamicSharedMemorySize, SMEM_TOT);

    transpose_all<<<2121, 128>>>(xyp, xzp, yzp, xv, yv, zv);
    sample_kernel<<<(NPTS + 127) / 128, 256, SMEM_TOT>>>(xyz, fv, out);
}